// round 4
// baseline (speedup 1.0000x reference)
#include <cuda_runtime.h>
#include <cuda_bf16.h>
#include <math.h>
#include <stdint.h>

#define NB 32
#define NN 512
#define ND 768
#define NL 4

#define FS ((size_t)NB * NN * ND)
#define AS ((size_t)NB * NN * NN)
#define DD ((size_t)ND * ND)

#define SCALE_LOGIT 0.03608439182435161f  // 1/sqrt(768)

// GEMM tiling
#define BM 256
#define BN 128
#define BK 32
#define PP 40                      // padded smem pitch (bf16 elems) per 32-k row
#define SM_AH 0
#define SM_AL (BM * PP)            // 10240
#define SM_BH (2 * BM * PP)        // 20480
#define SM_BL (2 * BM * PP + BN * PP)  // 25600
#define SM_STAGE (2 * BM * PP + 2 * BN * PP)  // 30720 bf16 elems
#define SMEM_BYTES (2 * SM_STAGE * 2)          // 122880 B dynamic

// ---------------- static device scratch ----------------
__device__ __align__(16) float g_F[NL][NB * NN * ND];          // fp32 features per layer
__device__ __align__(16) float g_adj[NL][NB * NN * NN];        // fp32 adj per layer
__device__ __align__(16) __nv_bfloat16 g_Fh[FS], g_Fl[FS];     // current F split
__device__ __align__(16) __nv_bfloat16 g_Wqh[NL * DD], g_Wql[NL * DD];
__device__ __align__(16) __nv_bfloat16 g_Wkh[NL * DD], g_Wkl[NL * DD];
__device__ __align__(16) __nv_bfloat16 g_Mth[NL * DD], g_Mtl[NL * DD];
__device__ __align__(16) __nv_bfloat16 g_Gh[FS], g_Gl[FS];
__device__ __align__(16) __nv_bfloat16 g_Fth[NB * ND * NN], g_Ftl[NB * ND * NN];
__device__ __align__(16) __nv_bfloat16 g_aTh[NB * NN * NN], g_aTl[NB * NN * NN];
__device__ float g_deg[NB * NN];
__device__ float g_dis[NB * NN];
__device__ float g_psum[NB];
__device__ float g_fullsum;
__device__ float g_l0;
__device__ float g_cacc[NB * NL];
__device__ float g_gacc[NB * NL];

// ---------------- small kernels ----------------
__global__ void k_zero() {
    int t = threadIdx.x;
    if (t == 0) { g_l0 = 0.f; g_fullsum = 0.f; }
    if (t < NB * NL) { g_cacc[t] = 0.f; g_gacc[t] = 0.f; }
}

__global__ void k_init(const float* __restrict__ pmask) {
    int b = blockIdx.x;
    float s = 0.f;
    for (int i = threadIdx.x; i < NN; i += 256) s += pmask[b * NN + i];
#pragma unroll
    for (int o = 16; o; o >>= 1) s += __shfl_xor_sync(0xffffffffu, s, o);
    __shared__ float sh[8];
    if ((threadIdx.x & 31) == 0) sh[threadIdx.x >> 5] = s;
    __syncthreads();
    if (threadIdx.x == 0) {
        float t = 0.f;
        for (int w = 0; w < 8; w++) t += sh[w];
        g_psum[b] = t;
        atomicAdd(&g_fullsum, t * t);
    }
}

__global__ void k_zero_deg() { g_deg[blockIdx.x * 256 + threadIdx.x] = 0.f; }

__global__ void k_dis() {
    int i = blockIdx.x * 256 + threadIdx.x;
    float d = g_deg[i];
    g_dis[i] = (d > 0.f) ? rsqrtf(fmaxf(d, 1e-12f)) : 0.f;
}

// split fp32 -> bf16 hi/lo (vectorized)
__global__ void k_split(const float4* __restrict__ x, __nv_bfloat162* __restrict__ h,
                        __nv_bfloat162* __restrict__ l, int n4) {
    int i = blockIdx.x * 256 + threadIdx.x;
    if (i >= n4) return;
    float4 v = x[i];
    __nv_bfloat16 h0 = __float2bfloat16(v.x), h1 = __float2bfloat16(v.y);
    __nv_bfloat16 h2 = __float2bfloat16(v.z), h3 = __float2bfloat16(v.w);
    h[2 * i]     = __nv_bfloat162(h0, h1);
    h[2 * i + 1] = __nv_bfloat162(h2, h3);
    l[2 * i]     = __nv_bfloat162(__float2bfloat16(v.x - __bfloat162float(h0)),
                                  __float2bfloat16(v.y - __bfloat162float(h1)));
    l[2 * i + 1] = __nv_bfloat162(__float2bfloat16(v.z - __bfloat162float(h2)),
                                  __float2bfloat16(v.w - __bfloat162float(h3)));
}

// Ft[b][d][n] = F[b][n][d] * dis[b][n], split hi/lo
__global__ void t_ft(const float* __restrict__ F, __nv_bfloat16* __restrict__ Fth,
                     __nv_bfloat16* __restrict__ Ftl) {
    int b = blockIdx.z;
    int d0 = blockIdx.x * 32, n0 = blockIdx.y * 32;
    __shared__ float t[32][33];
    int tx = threadIdx.x, ty = threadIdx.y;
#pragma unroll
    for (int r = 0; r < 32; r += 8) {
        int n = n0 + ty + r;
        t[ty + r][tx] = F[(size_t)b * NN * ND + (size_t)n * ND + d0 + tx] * g_dis[b * NN + n];
    }
    __syncthreads();
#pragma unroll
    for (int r = 0; r < 32; r += 8) {
        float v = t[tx][ty + r];
        size_t idx = (size_t)b * ND * NN + (size_t)(d0 + ty + r) * NN + n0 + tx;
        __nv_bfloat16 hb = __float2bfloat16(v);
        Fth[idx] = hb;
        Ftl[idx] = __float2bfloat16(v - __bfloat162float(hb));
    }
}

// adjT[b][m][n] = adj[b][n][m], split hi/lo
__global__ void t_adj(const float* __restrict__ adj, __nv_bfloat16* __restrict__ aTh,
                      __nv_bfloat16* __restrict__ aTl) {
    int b = blockIdx.z;
    int m0 = blockIdx.x * 32, n0 = blockIdx.y * 32;
    __shared__ float t[32][33];
    int tx = threadIdx.x, ty = threadIdx.y;
#pragma unroll
    for (int r = 0; r < 32; r += 8) {
        t[ty + r][tx] = adj[(size_t)b * NN * NN + (size_t)(n0 + ty + r) * NN + m0 + tx];
    }
    __syncthreads();
#pragma unroll
    for (int r = 0; r < 32; r += 8) {
        float v = t[tx][ty + r];
        size_t idx = (size_t)b * NN * NN + (size_t)(m0 + ty + r) * NN + n0 + tx;
        __nv_bfloat16 hb = __float2bfloat16(v);
        aTh[idx] = hb;
        aTl[idx] = __float2bfloat16(v - __bfloat162float(hb));
    }
}

// ---------------- bf16x3 NT MMA GEMM (pre-split operands) ----------------
__device__ __forceinline__ void mma16816(float* d, const uint32_t* a, uint32_t b0, uint32_t b1) {
    asm volatile(
        "mma.sync.aligned.m16n8k16.row.col.f32.bf16.bf16.f32 "
        "{%0,%1,%2,%3},{%4,%5,%6,%7},{%8,%9},{%0,%1,%2,%3};\n"
        : "+f"(d[0]), "+f"(d[1]), "+f"(d[2]), "+f"(d[3])
        : "r"(a[0]), "r"(a[1]), "r"(a[2]), "r"(a[3]), "r"(b0), "r"(b1));
}

__device__ __forceinline__ void cpa16(__nv_bfloat16* dst, const __nv_bfloat16* src) {
    uint32_t d = (uint32_t)__cvta_generic_to_shared(dst);
    asm volatile("cp.async.cg.shared.global [%0], [%1], 16;\n" :: "r"(d), "l"(src));
}

// EPI: 0 = split store (hi/lo), 1 = gate (sigmoid+mask+reductions), 2 = prop (dis scale, fp32 + hi/lo)
template <int EPI>
__global__ void __launch_bounds__(256, 1) k_mma(
    const __nv_bfloat16* __restrict__ Ahg, const __nv_bfloat16* __restrict__ Alg,
    const __nv_bfloat16* __restrict__ Bhg, const __nv_bfloat16* __restrict__ Blg,
    float* __restrict__ C, __nv_bfloat16* __restrict__ Ohi, __nv_bfloat16* __restrict__ Olo,
    int K, int lda, int ldb, int ldc,
    size_t bsA, size_t bsB, size_t bsC, size_t bsO,
    const float* __restrict__ pmask, int layer)
{
    extern __shared__ __align__(16) __nv_bfloat16 smem[];
    __shared__ float pmr[BM], pmc[BN];
    __shared__ float red[3][8];

    const int bz = blockIdx.z;
    Ahg += bz * bsA; Alg += bz * bsA;
    Bhg += bz * bsB; Blg += bz * bsB;
    if (C)   C   += bz * bsC;
    if (Ohi) { Ohi += bz * bsO; Olo += bz * bsO; }

    const int tid = threadIdx.x;
    const int m0 = blockIdx.y * BM;
    const int n0 = blockIdx.x * BN;

    if (EPI == 1) {
        pmr[tid] = pmask[bz * NN + m0 + tid];
        if (tid < BN) pmc[tid] = pmask[bz * NN + n0 + tid];
    }

    auto load_stage = [&](int s, int k0) {
        __nv_bfloat16* dst = smem + s * SM_STAGE;
#pragma unroll
        for (int i = 0; i < 4; i++) {
            int q = i * 256 + tid, row = q >> 2, c = q & 3;
            cpa16(dst + SM_AH + row * PP + c * 8, Ahg + (size_t)(m0 + row) * lda + k0 + c * 8);
            cpa16(dst + SM_AL + row * PP + c * 8, Alg + (size_t)(m0 + row) * lda + k0 + c * 8);
        }
#pragma unroll
        for (int i = 0; i < 2; i++) {
            int q = i * 256 + tid, row = q >> 2, c = q & 3;
            cpa16(dst + SM_BH + row * PP + c * 8, Bhg + (size_t)(n0 + row) * ldb + k0 + c * 8);
            cpa16(dst + SM_BL + row * PP + c * 8, Blg + (size_t)(n0 + row) * ldb + k0 + c * 8);
        }
        asm volatile("cp.async.commit_group;\n");
    };

    float acc[4][8][4];
#pragma unroll
    for (int mi = 0; mi < 4; mi++)
#pragma unroll
        for (int nj = 0; nj < 8; nj++)
#pragma unroll
            for (int q = 0; q < 4; q++) acc[mi][nj][q] = 0.f;

    const int lane = tid & 31;
    const int wid = tid >> 5;
    const int g = lane >> 2, t4 = lane & 3;
    const int wr = (wid & 3) * 64;   // warp row base (M)
    const int wc = (wid >> 2) * 64;  // warp col base (N)

    load_stage(0, 0);
    const int KT = K / BK;
    for (int kt = 0; kt < KT; kt++) {
        const int s = kt & 1;
        if (kt + 1 < KT) {
            load_stage(s ^ 1, (kt + 1) * BK);
            asm volatile("cp.async.wait_group 1;\n");
        } else {
            asm volatile("cp.async.wait_group 0;\n");
        }
        __syncthreads();

        const __nv_bfloat16* sb = smem + s * SM_STAGE;
        const __nv_bfloat16* sAh = sb + SM_AH;
        const __nv_bfloat16* sAl = sb + SM_AL;
        const __nv_bfloat16* sBh = sb + SM_BH;
        const __nv_bfloat16* sBl = sb + SM_BL;

#pragma unroll
        for (int kk = 0; kk < BK; kk += 16) {
            uint32_t ah[4][4], al[4][4];
#pragma unroll
            for (int mi = 0; mi < 4; mi++) {
                const int r = wr + 16 * mi + g;
                const __nv_bfloat16* ph = &sAh[r * PP + kk + 2 * t4];
                const __nv_bfloat16* pl = &sAl[r * PP + kk + 2 * t4];
                ah[mi][0] = *(const uint32_t*)(ph);
                ah[mi][1] = *(const uint32_t*)(ph + 8 * PP);
                ah[mi][2] = *(const uint32_t*)(ph + 8);
                ah[mi][3] = *(const uint32_t*)(ph + 8 * PP + 8);
                al[mi][0] = *(const uint32_t*)(pl);
                al[mi][1] = *(const uint32_t*)(pl + 8 * PP);
                al[mi][2] = *(const uint32_t*)(pl + 8);
                al[mi][3] = *(const uint32_t*)(pl + 8 * PP + 8);
            }
#pragma unroll
            for (int nj = 0; nj < 8; nj++) {
                const int c = wc + 8 * nj + g;
                const __nv_bfloat16* qh = &sBh[c * PP + kk + 2 * t4];
                const __nv_bfloat16* ql = &sBl[c * PP + kk + 2 * t4];
                uint32_t bh0 = *(const uint32_t*)(qh);
                uint32_t bh1 = *(const uint32_t*)(qh + 8);
                uint32_t bl0 = *(const uint32_t*)(ql);
                uint32_t bl1 = *(const uint32_t*)(ql + 8);
#pragma unroll
                for (int mi = 0; mi < 4; mi++) {
                    mma16816(acc[mi][nj], ah[mi], bh0, bh1);
                    mma16816(acc[mi][nj], ah[mi], bl0, bl1);
                    mma16816(acc[mi][nj], al[mi], bh0, bh1);
                }
            }
        }
        __syncthreads();
    }

    // ---------------- epilogues ----------------
    if (EPI == 0) {
#pragma unroll
        for (int mi = 0; mi < 4; mi++) {
            const int R = m0 + wr + 16 * mi + g;
#pragma unroll
            for (int nj = 0; nj < 8; nj++) {
                const int Cc = n0 + wc + 8 * nj + 2 * t4;
#pragma unroll
                for (int half = 0; half < 2; half++) {
                    float v0 = acc[mi][nj][2 * half], v1 = acc[mi][nj][2 * half + 1];
                    size_t idx = (size_t)(R + 8 * half) * ldc + Cc;
                    __nv_bfloat16 h0 = __float2bfloat16(v0), h1 = __float2bfloat16(v1);
                    *(__nv_bfloat162*)(Ohi + idx) = __nv_bfloat162(h0, h1);
                    *(__nv_bfloat162*)(Olo + idx) =
                        __nv_bfloat162(__float2bfloat16(v0 - __bfloat162float(h0)),
                                       __float2bfloat16(v1 - __bfloat162float(h1)));
                }
            }
        }
    } else if (EPI == 2) {
#pragma unroll
        for (int mi = 0; mi < 4; mi++) {
            const int R = m0 + wr + 16 * mi + g;
            const float s1 = g_dis[bz * NN + R];
            const float s2 = g_dis[bz * NN + R + 8];
#pragma unroll
            for (int nj = 0; nj < 8; nj++) {
                const int Cc = n0 + wc + 8 * nj + 2 * t4;
                float v0 = acc[mi][nj][0] * s1, v1 = acc[mi][nj][1] * s1;
                float v2 = acc[mi][nj][2] * s2, v3 = acc[mi][nj][3] * s2;
                size_t i1 = (size_t)R * ldc + Cc, i2 = (size_t)(R + 8) * ldc + Cc;
                *(float2*)(C + i1) = make_float2(v0, v1);
                *(float2*)(C + i2) = make_float2(v2, v3);
                __nv_bfloat16 h0 = __float2bfloat16(v0), h1 = __float2bfloat16(v1);
                __nv_bfloat16 h2 = __float2bfloat16(v2), h3 = __float2bfloat16(v3);
                *(__nv_bfloat162*)(Ohi + i1) = __nv_bfloat162(h0, h1);
                *(__nv_bfloat162*)(Ohi + i2) = __nv_bfloat162(h2, h3);
                *(__nv_bfloat162*)(Olo + i1) =
                    __nv_bfloat162(__float2bfloat16(v0 - __bfloat162float(h0)),
                                   __float2bfloat16(v1 - __bfloat162float(h1)));
                *(__nv_bfloat162*)(Olo + i2) =
                    __nv_bfloat162(__float2bfloat16(v2 - __bfloat162float(h2)),
                                   __float2bfloat16(v3 - __bfloat162float(h3)));
            }
        }
    } else {  // EPI == 1 : gate
        float l0loc = 0.f, cloc = 0.f, gloc = 0.f;
#pragma unroll
        for (int mi = 0; mi < 4; mi++) {
            const int Rl = wr + 16 * mi + g;
            const int R = m0 + Rl;
            const float pr1 = pmr[Rl], pr2 = pmr[Rl + 8];
            float row1 = 0.f, row2 = 0.f;
#pragma unroll
            for (int nj = 0; nj < 8; nj++) {
                const int Ccl = wc + 8 * nj + 2 * t4;
                const int Cc = n0 + Ccl;
                const float pc0 = pmc[Ccl], pc1 = pmc[Ccl + 1];
                float v00 = (1.f / (1.f + expf(-acc[mi][nj][0] * SCALE_LOGIT))) * pr1 * pc0;
                float v01 = (1.f / (1.f + expf(-acc[mi][nj][1] * SCALE_LOGIT))) * pr1 * pc1;
                float v10 = (1.f / (1.f + expf(-acc[mi][nj][2] * SCALE_LOGIT))) * pr2 * pc0;
                float v11 = (1.f / (1.f + expf(-acc[mi][nj][3] * SCALE_LOGIT))) * pr2 * pc1;
                row1 += v00 + v01;
                row2 += v10 + v11;
                l0loc += v00 + v01 + v10 + v11;
                const bool m0ok = (Cc < NN - 1), m1ok = (Cc + 1 < NN - 1);
                float e1 = (m0ok ? v00 : 0.f) + (m1ok ? v01 : 0.f);
                float e2 = (m0ok ? v10 : 0.f) + (m1ok ? v11 : 0.f);
                if (R == NN - 1) cloc += e1; else gloc += e1;
                if (R + 8 == NN - 1) cloc += e2; else gloc += e2;
                *(float2*)(C + (size_t)R * ldc + Cc) = make_float2(v00, v01);
                *(float2*)(C + (size_t)(R + 8) * ldc + Cc) = make_float2(v10, v11);
            }
            row1 += __shfl_xor_sync(0xffffffffu, row1, 1);
            row1 += __shfl_xor_sync(0xffffffffu, row1, 2);
            row2 += __shfl_xor_sync(0xffffffffu, row2, 1);
            row2 += __shfl_xor_sync(0xffffffffu, row2, 2);
            if (t4 == 0) {
                atomicAdd(&g_deg[bz * NN + R], row1);
                atomicAdd(&g_deg[bz * NN + R + 8], row2);
            }
        }
#pragma unroll
        for (int o = 16; o; o >>= 1) {
            l0loc += __shfl_xor_sync(0xffffffffu, l0loc, o);
            cloc  += __shfl_xor_sync(0xffffffffu, cloc, o);
            gloc  += __shfl_xor_sync(0xffffffffu, gloc, o);
        }
        if (lane == 0) { red[0][wid] = l0loc; red[1][wid] = cloc; red[2][wid] = gloc; }
        __syncthreads();
        if (tid == 0) {
            float a = 0.f, c = 0.f, gg = 0.f;
            for (int w = 0; w < 8; w++) { a += red[0][w]; c += red[1][w]; gg += red[2][w]; }
            atomicAdd(&g_l0, a);
            atomicAdd(&g_cacc[bz * NL + layer], c);
            atomicAdd(&g_gacc[bz * NL + layer], gg);
        }
    }
}

// ---------------- attention-pool epilogue ----------------
__global__ void __launch_bounds__(256) k_final(
    const float* __restrict__ F0, const float* __restrict__ projw,
    const float* __restrict__ projb, float* __restrict__ out, float* __restrict__ retain)
{
    const int bn = blockIdx.x;
    const float* p0 = F0 + (size_t)bn * ND;
    const float* p1 = g_F[0] + (size_t)bn * ND;
    const float* p2 = g_F[1] + (size_t)bn * ND;
    const float* p3 = g_F[2] + (size_t)bn * ND;
    const float* p4 = g_F[3] + (size_t)bn * ND;
    float d0 = 0.f, d1 = 0.f, d2 = 0.f, d3 = 0.f, d4 = 0.f;
    for (int i = threadIdx.x; i < ND; i += 256) {
        float w = projw[i];
        d0 += p0[i] * w; d1 += p1[i] * w; d2 += p2[i] * w; d3 += p3[i] * w; d4 += p4[i] * w;
    }
#pragma unroll
    for (int o = 16; o; o >>= 1) {
        d0 += __shfl_xor_sync(0xffffffffu, d0, o);
        d1 += __shfl_xor_sync(0xffffffffu, d1, o);
        d2 += __shfl_xor_sync(0xffffffffu, d2, o);
        d3 += __shfl_xor_sync(0xffffffffu, d3, o);
        d4 += __shfl_xor_sync(0xffffffffu, d4, o);
    }
    __shared__ float sh[5][8];
    __shared__ float r[5];
    const int wid = threadIdx.x >> 5, lane = threadIdx.x & 31;
    if (lane == 0) { sh[0][wid] = d0; sh[1][wid] = d1; sh[2][wid] = d2; sh[3][wid] = d3; sh[4][wid] = d4; }
    __syncthreads();
    if (threadIdx.x < 5) {
        float t = 0.f;
        for (int w = 0; w < 8; w++) t += sh[threadIdx.x][w];
        float rr = 1.f / (1.f + expf(-(t + projb[0])));
        r[threadIdx.x] = rr;
        retain[(size_t)bn * (NL + 1) + threadIdx.x] = rr;
    }
    __syncthreads();
    const float r0 = r[0], r1 = r[1], r2 = r[2], r3 = r[3], r4 = r[4];
    for (int i = threadIdx.x; i < ND; i += 256) {
        out[(size_t)bn * ND + i] =
            r0 * p0[i] + r1 * p1[i] + r2 * p2[i] + r3 * p3[i] + r4 * p4[i];
    }
}

__global__ void k_repack(float* __restrict__ adjs_out) {
    size_t i = (size_t)blockIdx.x * 256 + threadIdx.x;
    float4 v = make_float4(g_adj[0][i], g_adj[1][i], g_adj[2][i], g_adj[3][i]);
    ((float4*)adjs_out)[i] = v;
}

__global__ void k_finalize(float* __restrict__ o_l0, float* __restrict__ o_c, float* __restrict__ o_g) {
    int t = threadIdx.x;
    if (t == 0) *o_l0 = g_l0 / ((g_fullsum + 1e-8f) * (float)NL);
    if (t < NB * NL) {
        int b = t / NL;
        float ps = g_psum[b];
        o_c[t] = g_cacc[t] / ps;
        o_g[t] = g_gacc[t] / (ps * ps);
    }
}

// ---------------- host orchestration ----------------
extern "C" void kernel_launch(void* const* d_in, const int* in_sizes, int n_in,
                              void* d_out, int out_size)
{
    (void)in_sizes; (void)n_in; (void)out_size;
    const float* pmask   = (const float*)d_in[0];
    const float* feature = (const float*)d_in[1];
    const float* Wq      = (const float*)d_in[2];
    const float* Wk      = (const float*)d_in[3];
    const float* projw   = (const float*)d_in[4];
    const float* projb   = (const float*)d_in[5];

    float* out    = (float*)d_out;
    float* retain = out + FS;
    float* adjs   = retain + (size_t)NB * NN * (NL + 1);
    float* o_l0   = adjs + AS * NL;
    float* o_c    = o_l0 + 1;
    float* o_g    = o_c + NB * NL;

    cudaFuncSetAttribute((const void*)&k_mma<0>, cudaFuncAttributeMaxDynamicSharedMemorySize, SMEM_BYTES);
    cudaFuncSetAttribute((const void*)&k_mma<1>, cudaFuncAttributeMaxDynamicSharedMemorySize, SMEM_BYTES);
    cudaFuncSetAttribute((const void*)&k_mma<2>, cudaFuncAttributeMaxDynamicSharedMemorySize, SMEM_BYTES);

    // device symbol addresses
    float *pF, *pAdj;
    __nv_bfloat16 *pFh, *pFl, *pWqh, *pWql, *pWkh, *pWkl, *pMth, *pMtl;
    __nv_bfloat16 *pGh, *pGl, *pFth, *pFtl, *paTh, *paTl;
    cudaGetSymbolAddress((void**)&pF, g_F);
    cudaGetSymbolAddress((void**)&pAdj, g_adj);
    cudaGetSymbolAddress((void**)&pFh, g_Fh);
    cudaGetSymbolAddress((void**)&pFl, g_Fl);
    cudaGetSymbolAddress((void**)&pWqh, g_Wqh);
    cudaGetSymbolAddress((void**)&pWql, g_Wql);
    cudaGetSymbolAddress((void**)&pWkh, g_Wkh);
    cudaGetSymbolAddress((void**)&pWkl, g_Wkl);
    cudaGetSymbolAddress((void**)&pMth, g_Mth);
    cudaGetSymbolAddress((void**)&pMtl, g_Mtl);
    cudaGetSymbolAddress((void**)&pGh, g_Gh);
    cudaGetSymbolAddress((void**)&pGl, g_Gl);
    cudaGetSymbolAddress((void**)&pFth, g_Fth);
    cudaGetSymbolAddress((void**)&pFtl, g_Ftl);
    cudaGetSymbolAddress((void**)&paTh, g_aTh);
    cudaGetSymbolAddress((void**)&paTl, g_aTl);

    k_zero<<<1, 128>>>();
    k_init<<<NB, 256>>>(pmask);

    // split inputs to bf16 hi/lo
    k_split<<<(int)(FS / 4 + 255) / 256, 256>>>((const float4*)feature,
        (__nv_bfloat162*)pFh, (__nv_bfloat162*)pFl, (int)(FS / 4));
    k_split<<<(int)(NL * DD / 4 + 255) / 256, 256>>>((const float4*)Wq,
        (__nv_bfloat162*)pWqh, (__nv_bfloat162*)pWql, (int)(NL * DD / 4));
    k_split<<<(int)(NL * DD / 4 + 255) / 256, 256>>>((const float4*)Wk,
        (__nv_bfloat162*)pWkh, (__nv_bfloat162*)pWkl, (int)(NL * DD / 4));

    // Mt[l] = Wk[l] * Wq[l]^T  (hi/lo out), batched over layers
    k_mma<0><<<dim3(ND / BN, ND / BM, NL), 256, SMEM_BYTES>>>(
        pWkh, pWkl, pWqh, pWql, nullptr, pMth, pMtl,
        ND, ND, ND, ND, DD, DD, 0, DD, nullptr, 0);

    const float* Fcur = feature;
    for (int l = 0; l < NL; l++) {
        k_zero_deg<<<64, 256>>>();
        // G = F * Mt[l]^T  (hi/lo out), M = B*N flattened
        k_mma<0><<<dim3(ND / BN, (NB * NN) / BM, 1), 256, SMEM_BYTES>>>(
            pFh, pFl, pMth + (size_t)l * DD, pMtl + (size_t)l * DD,
            nullptr, pGh, pGl,
            ND, ND, ND, ND, 0, 0, 0, 0, nullptr, 0);
        // adj = sigmoid(scale * G F^T) * mask (+deg/c/g/l0)
        k_mma<1><<<dim3(NN / BN, NN / BM, NB), 256, SMEM_BYTES>>>(
            pGh, pGl, pFh, pFl, pAdj + (size_t)l * AS, nullptr, nullptr,
            ND, ND, ND, NN,
            (size_t)NN * ND, (size_t)NN * ND, (size_t)NN * NN, 0, pmask, l);
        k_dis<<<64, 256>>>();
        // adjT hi/lo + Ft hi/lo (dis folded)
        t_adj<<<dim3(NN / 32, NN / 32, NB), dim3(32, 8)>>>(pAdj + (size_t)l * AS, paTh, paTl);
        t_ft<<<dim3(ND / 32, NN / 32, NB), dim3(32, 8)>>>(Fcur, pFth, pFtl);
        // Fout[m,d] = dis[m] * sum_n adjT[m,n]*Ft[d,n]  (fp32 + hi/lo for next layer)
        float* Fnext = pF + (size_t)l * FS;
        k_mma<2><<<dim3(ND / BN, NN / BM, NB), 256, SMEM_BYTES>>>(
            paTh, paTl, pFth, pFtl, Fnext, pFh, pFl,
            NN, NN, NN, ND,
            (size_t)NN * NN, (size_t)ND * NN, (size_t)NN * ND, (size_t)NN * ND, nullptr, 0);
        Fcur = Fnext;
    }

    k_final<<<NB * NN, 256>>>(feature, projw, projb, out, retain);
    k_repack<<<(int)(AS / 256), 256>>>(adjs);
    k_finalize<<<1, 128>>>(o_l0, o_c, o_g);
}

// round 6
// speedup vs baseline: 1.9643x; 1.9643x over previous
#include <cuda_runtime.h>
#include <cuda_fp16.h>
#include <math.h>
#include <stdint.h>

#define NB 32
#define NN 512
#define ND 768
#define NL 4
#define FS ((size_t)NB * NN * ND)
#define AS ((size_t)NB * NN * NN)
#define DD ((size_t)ND * ND)
#define SCALE_LOGIT 0.03608439182435161f

// GEMM tiling (proven R3 structure, single fp16 operands)
#define BM 256
#define BN 128
#define BK 32
#define PP 40
#define SM_A 0
#define SM_B (BM * PP)                 // 10240 halves
#define SM_STAGE ((BM + BN) * PP)      // 15360 halves
#define SMEM_BYTES (2 * SM_STAGE * 2)  // 61440 B

// ---------------- static device scratch ----------------
__device__ __align__(16) float g_F[NL][NB * NN * ND];   // fp32 features per layer
__device__ __align__(16) float g_adj[NL][NB * NN * NN]; // fp32 adj per layer
__device__ __align__(16) __half g_Fp[FS];               // current F fp16
__device__ __align__(16) __half g_Wq16[NL * DD], g_Wk16[NL * DD];
__device__ __align__(16) __half g_Mt[NL * DD];
__device__ __align__(16) __half g_Ft[NB * ND * NN];     // shared: G then Ft per layer
__device__ __align__(16) __half g_aT[NB * NN * NN];     // adj^T fp16
__device__ float g_deg[NB * NN], g_dis[NB * NN], g_psum[NB];
__device__ float g_fullsum, g_l0, g_cacc[NB * NL], g_gacc[NB * NL];

// ---------------- small kernels ----------------
__global__ void k_zero() {
    int t = threadIdx.x;
    if (t == 0) { g_l0 = 0.f; g_fullsum = 0.f; }
    if (t < NB * NL) { g_cacc[t] = 0.f; g_gacc[t] = 0.f; }
}

__global__ void k_init(const float* __restrict__ pmask) {
    int b = blockIdx.x;
    float s = 0.f;
    for (int i = threadIdx.x; i < NN; i += 256) s += pmask[b * NN + i];
#pragma unroll
    for (int o = 16; o; o >>= 1) s += __shfl_xor_sync(0xffffffffu, s, o);
    __shared__ float sh[8];
    if ((threadIdx.x & 31) == 0) sh[threadIdx.x >> 5] = s;
    __syncthreads();
    if (threadIdx.x == 0) {
        float t = 0.f;
        for (int w = 0; w < 8; w++) t += sh[w];
        g_psum[b] = t;
        atomicAdd(&g_fullsum, t * t);
    }
}

__global__ void k_zero_deg() { g_deg[blockIdx.x * 256 + threadIdx.x] = 0.f; }

__global__ void k_dis() {
    int i = blockIdx.x * 256 + threadIdx.x;
    float d = g_deg[i];
    g_dis[i] = (d > 0.f) ? rsqrtf(fmaxf(d, 1e-12f)) : 0.f;
}

// fp32 -> fp16 convert
__global__ void k_cvt(const float4* __restrict__ x, __half2* __restrict__ h, int n4) {
    int i = blockIdx.x * 256 + threadIdx.x;
    if (i >= n4) return;
    float4 v = x[i];
    h[2 * i]     = __floats2half2_rn(v.x, v.y);
    h[2 * i + 1] = __floats2half2_rn(v.z, v.w);
}

// Ft[b][d][n] = F[b][n][d] * dis[b][n], fp16
__global__ void t_ft(const float* __restrict__ F, __half* __restrict__ Ft) {
    int b = blockIdx.z, d0 = blockIdx.x * 32, n0 = blockIdx.y * 32;
    __shared__ float t[32][33];
    int tx = threadIdx.x, ty = threadIdx.y;
#pragma unroll
    for (int r = 0; r < 32; r += 8) {
        int n = n0 + ty + r;
        t[ty + r][tx] = F[(size_t)b * NN * ND + (size_t)n * ND + d0 + tx] * g_dis[b * NN + n];
    }
    __syncthreads();
#pragma unroll
    for (int r = 0; r < 32; r += 8) {
        Ft[(size_t)b * ND * NN + (size_t)(d0 + ty + r) * NN + n0 + tx] = __float2half(t[tx][ty + r]);
    }
}

// ---------------- fp16 NT MMA GEMM ----------------
__device__ __forceinline__ void mma16816(float* d, const uint32_t* a, uint32_t b0, uint32_t b1) {
    asm volatile(
        "mma.sync.aligned.m16n8k16.row.col.f32.f16.f16.f32 "
        "{%0,%1,%2,%3},{%4,%5,%6,%7},{%8,%9},{%0,%1,%2,%3};\n"
        : "+f"(d[0]), "+f"(d[1]), "+f"(d[2]), "+f"(d[3])
        : "r"(a[0]), "r"(a[1]), "r"(a[2]), "r"(a[3]), "r"(b0), "r"(b1));
}

__device__ __forceinline__ void cpa16(__half* dst, const __half* src) {
    uint32_t d = (uint32_t)__cvta_generic_to_shared(dst);
    asm volatile("cp.async.cg.shared.global [%0], [%1], 16;\n" :: "r"(d), "l"(src));
}

// EPI: 0 = fp16 store, 1 = gate (sigmoid+mask+reductions+adjT), 2 = prop (dis scale, fp32 + fp16)
template <int EPI>
__global__ void __launch_bounds__(256, 1) k_mma(
    const __half* __restrict__ Ag, const __half* __restrict__ Bg,
    float* __restrict__ C, __half* __restrict__ O,
    int K, int lda, int ldb, int ldc,
    size_t bsA, size_t bsB, size_t bsC, size_t bsO,
    const float* __restrict__ pmask, int layer)
{
    extern __shared__ __align__(16) __half smem[];
    __shared__ float pmr[BM], pmc[BN];
    __shared__ float red[3][8];

    const int bz = blockIdx.z;
    Ag += bz * bsA; Bg += bz * bsB;
    if (C) C += bz * bsC;
    if (O) O += bz * bsO;

    const int tid = threadIdx.x;
    const int m0 = blockIdx.y * BM;
    const int n0 = blockIdx.x * BN;

    if (EPI == 1) {
        pmr[tid] = pmask[bz * NN + m0 + tid];
        if (tid < BN) pmc[tid] = pmask[bz * NN + n0 + tid];
    }

    auto load_stage = [&](int s, int k0) {
        __half* dst = smem + s * SM_STAGE;
#pragma unroll
        for (int i = 0; i < 4; i++) {
            int q = i * 256 + tid, row = q >> 2, c = q & 3;
            cpa16(dst + SM_A + row * PP + c * 8, Ag + (size_t)(m0 + row) * lda + k0 + c * 8);
        }
#pragma unroll
        for (int i = 0; i < 2; i++) {
            int q = i * 256 + tid, row = q >> 2, c = q & 3;
            cpa16(dst + SM_B + row * PP + c * 8, Bg + (size_t)(n0 + row) * ldb + k0 + c * 8);
        }
        asm volatile("cp.async.commit_group;\n");
    };

    float acc[4][8][4];
#pragma unroll
    for (int mi = 0; mi < 4; mi++)
#pragma unroll
        for (int nj = 0; nj < 8; nj++)
#pragma unroll
            for (int q = 0; q < 4; q++) acc[mi][nj][q] = 0.f;

    const int lane = tid & 31;
    const int wid = tid >> 5;
    const int g = lane >> 2, t4 = lane & 3;
    const int wr = (wid & 3) * 64;   // warp row base (M)
    const int wc = (wid >> 2) * 64;  // warp col base (N)

    load_stage(0, 0);
    const int KT = K / BK;
    for (int kt = 0; kt < KT; kt++) {
        const int s = kt & 1;
        if (kt + 1 < KT) {
            load_stage(s ^ 1, (kt + 1) * BK);
            asm volatile("cp.async.wait_group 1;\n");
        } else {
            asm volatile("cp.async.wait_group 0;\n");
        }
        __syncthreads();

        const __half* sA = smem + s * SM_STAGE + SM_A;
        const __half* sB = smem + s * SM_STAGE + SM_B;

#pragma unroll
        for (int kk = 0; kk < BK; kk += 16) {
            uint32_t af[4][4];
#pragma unroll
            for (int mi = 0; mi < 4; mi++) {
                const __half* p = &sA[(wr + 16 * mi + g) * PP + kk + 2 * t4];
                af[mi][0] = *(const uint32_t*)(p);
                af[mi][1] = *(const uint32_t*)(p + 8 * PP);
                af[mi][2] = *(const uint32_t*)(p + 8);
                af[mi][3] = *(const uint32_t*)(p + 8 * PP + 8);
            }
#pragma unroll
            for (int nj = 0; nj < 8; nj++) {
                const __half* q = &sB[(wc + 8 * nj + g) * PP + kk + 2 * t4];
                uint32_t b0 = *(const uint32_t*)(q);
                uint32_t b1 = *(const uint32_t*)(q + 8);
#pragma unroll
                for (int mi = 0; mi < 4; mi++)
                    mma16816(acc[mi][nj], af[mi], b0, b1);
            }
        }
        __syncthreads();
    }

    // ---------------- epilogues ----------------
    if (EPI == 0) {
#pragma unroll
        for (int mi = 0; mi < 4; mi++) {
            const int R = m0 + wr + 16 * mi + g;
#pragma unroll
            for (int nj = 0; nj < 8; nj++) {
                const int Cc = n0 + wc + 8 * nj + 2 * t4;
                *(__half2*)(O + (size_t)R * ldc + Cc) =
                    __floats2half2_rn(acc[mi][nj][0], acc[mi][nj][1]);
                *(__half2*)(O + (size_t)(R + 8) * ldc + Cc) =
                    __floats2half2_rn(acc[mi][nj][2], acc[mi][nj][3]);
            }
        }
    } else if (EPI == 2) {
#pragma unroll
        for (int mi = 0; mi < 4; mi++) {
            const int R = m0 + wr + 16 * mi + g;
            const float s1 = g_dis[bz * NN + R];
            const float s2 = g_dis[bz * NN + R + 8];
#pragma unroll
            for (int nj = 0; nj < 8; nj++) {
                const int Cc = n0 + wc + 8 * nj + 2 * t4;
                float v0 = acc[mi][nj][0] * s1, v1 = acc[mi][nj][1] * s1;
                float v2 = acc[mi][nj][2] * s2, v3 = acc[mi][nj][3] * s2;
                size_t i1 = (size_t)R * ldc + Cc, i2 = (size_t)(R + 8) * ldc + Cc;
                *(float2*)(C + i1) = make_float2(v0, v1);
                *(float2*)(C + i2) = make_float2(v2, v3);
                *(__half2*)(O + i1) = __floats2half2_rn(v0, v1);
                *(__half2*)(O + i2) = __floats2half2_rn(v2, v3);
            }
        }
    } else {  // EPI == 1 : gate. M-dim = adj row n, N-dim = adj col m. O = adjT fp16.
        float l0loc = 0.f, cloc = 0.f, gloc = 0.f;
#pragma unroll
        for (int mi = 0; mi < 4; mi++) {
            const int Rl = wr + 16 * mi + g;
            const int R = m0 + Rl;
            const float pr1 = pmr[Rl], pr2 = pmr[Rl + 8];
            float row1 = 0.f, row2 = 0.f;
#pragma unroll
            for (int nj = 0; nj < 8; nj++) {
                const int Ccl = wc + 8 * nj + 2 * t4;
                const int Cc = n0 + Ccl;
                const float pc0 = pmc[Ccl], pc1 = pmc[Ccl + 1];
                float v00 = (1.f / (1.f + expf(-acc[mi][nj][0] * SCALE_LOGIT))) * pr1 * pc0;
                float v01 = (1.f / (1.f + expf(-acc[mi][nj][1] * SCALE_LOGIT))) * pr1 * pc1;
                float v10 = (1.f / (1.f + expf(-acc[mi][nj][2] * SCALE_LOGIT))) * pr2 * pc0;
                float v11 = (1.f / (1.f + expf(-acc[mi][nj][3] * SCALE_LOGIT))) * pr2 * pc1;
                row1 += v00 + v01;
                row2 += v10 + v11;
                l0loc += v00 + v01 + v10 + v11;
                const bool c0ok = (Cc < NN - 1), c1ok = (Cc + 1 < NN - 1);
                float e1 = (c0ok ? v00 : 0.f) + (c1ok ? v01 : 0.f);
                float e2 = (c0ok ? v10 : 0.f) + (c1ok ? v11 : 0.f);
                if (R == NN - 1) cloc += e1; else gloc += e1;
                if (R + 8 == NN - 1) cloc += e2; else gloc += e2;
                *(float2*)(C + (size_t)R * ldc + Cc) = make_float2(v00, v01);
                *(float2*)(C + (size_t)(R + 8) * ldc + Cc) = make_float2(v10, v11);
                // adjT[m][n] = adj[n][m]
                O[(size_t)Cc * NN + R]           = __float2half(v00);
                O[(size_t)(Cc + 1) * NN + R]     = __float2half(v01);
                O[(size_t)Cc * NN + R + 8]       = __float2half(v10);
                O[(size_t)(Cc + 1) * NN + R + 8] = __float2half(v11);
            }
            row1 += __shfl_xor_sync(0xffffffffu, row1, 1);
            row1 += __shfl_xor_sync(0xffffffffu, row1, 2);
            row2 += __shfl_xor_sync(0xffffffffu, row2, 1);
            row2 += __shfl_xor_sync(0xffffffffu, row2, 2);
            if (t4 == 0) {
                atomicAdd(&g_deg[bz * NN + R], row1);
                atomicAdd(&g_deg[bz * NN + R + 8], row2);
            }
        }
#pragma unroll
        for (int o = 16; o; o >>= 1) {
            l0loc += __shfl_xor_sync(0xffffffffu, l0loc, o);
            cloc  += __shfl_xor_sync(0xffffffffu, cloc, o);
            gloc  += __shfl_xor_sync(0xffffffffu, gloc, o);
        }
        if (lane == 0) { red[0][wid] = l0loc; red[1][wid] = cloc; red[2][wid] = gloc; }
        __syncthreads();
        if (tid == 0) {
            float a = 0.f, c = 0.f, gg = 0.f;
            for (int w = 0; w < 8; w++) { a += red[0][w]; c += red[1][w]; gg += red[2][w]; }
            atomicAdd(&g_l0, a);
            atomicAdd(&g_cacc[bz * NL + layer], c);
            atomicAdd(&g_gacc[bz * NL + layer], gg);
        }
    }
}

// ---------------- attention-pool epilogue ----------------
__global__ void __launch_bounds__(256) k_final(
    const float* __restrict__ F0, const float* __restrict__ projw,
    const float* __restrict__ projb, float* __restrict__ out, float* __restrict__ retain)
{
    const int bn = blockIdx.x;
    const float* p0 = F0 + (size_t)bn * ND;
    const float* p1 = g_F[0] + (size_t)bn * ND;
    const float* p2 = g_F[1] + (size_t)bn * ND;
    const float* p3 = g_F[2] + (size_t)bn * ND;
    const float* p4 = g_F[3] + (size_t)bn * ND;
    float d0 = 0.f, d1 = 0.f, d2 = 0.f, d3 = 0.f, d4 = 0.f;
    for (int i = threadIdx.x; i < ND; i += 256) {
        float w = projw[i];
        d0 += p0[i] * w; d1 += p1[i] * w; d2 += p2[i] * w; d3 += p3[i] * w; d4 += p4[i] * w;
    }
#pragma unroll
    for (int o = 16; o; o >>= 1) {
        d0 += __shfl_xor_sync(0xffffffffu, d0, o);
        d1 += __shfl_xor_sync(0xffffffffu, d1, o);
        d2 += __shfl_xor_sync(0xffffffffu, d2, o);
        d3 += __shfl_xor_sync(0xffffffffu, d3, o);
        d4 += __shfl_xor_sync(0xffffffffu, d4, o);
    }
    __shared__ float sh[5][8], r[5];
    const int wid = threadIdx.x >> 5, lane = threadIdx.x & 31;
    if (lane == 0) { sh[0][wid] = d0; sh[1][wid] = d1; sh[2][wid] = d2; sh[3][wid] = d3; sh[4][wid] = d4; }
    __syncthreads();
    if (threadIdx.x < 5) {
        float t = 0.f;
        for (int w = 0; w < 8; w++) t += sh[threadIdx.x][w];
        float rr = 1.f / (1.f + expf(-(t + projb[0])));
        r[threadIdx.x] = rr;
        retain[(size_t)bn * (NL + 1) + threadIdx.x] = rr;
    }
    __syncthreads();
    const float r0 = r[0], r1 = r[1], r2 = r[2], r3 = r[3], r4 = r[4];
    for (int i = threadIdx.x; i < ND; i += 256)
        out[(size_t)bn * ND + i] = r0 * p0[i] + r1 * p1[i] + r2 * p2[i] + r3 * p3[i] + r4 * p4[i];
}

__global__ void k_repack(float* __restrict__ adjs_out) {
    size_t i = (size_t)blockIdx.x * 256 + threadIdx.x;
    ((float4*)adjs_out)[i] = make_float4(g_adj[0][i], g_adj[1][i], g_adj[2][i], g_adj[3][i]);
}

__global__ void k_finalize(float* __restrict__ o_l0, float* __restrict__ o_c, float* __restrict__ o_g) {
    int t = threadIdx.x;
    if (t == 0) *o_l0 = g_l0 / ((g_fullsum + 1e-8f) * (float)NL);
    if (t < NB * NL) {
        int b = t / NL;
        float ps = g_psum[b];
        o_c[t] = g_cacc[t] / ps;
        o_g[t] = g_gacc[t] / (ps * ps);
    }
}

// ---------------- host orchestration ----------------
extern "C" void kernel_launch(void* const* d_in, const int* in_sizes, int n_in,
                              void* d_out, int out_size)
{
    (void)in_sizes; (void)n_in; (void)out_size;
    const float* pmask   = (const float*)d_in[0];
    const float* feature = (const float*)d_in[1];
    const float* Wq      = (const float*)d_in[2];
    const float* Wk      = (const float*)d_in[3];
    const float* projw   = (const float*)d_in[4];
    const float* projb   = (const float*)d_in[5];

    float* out    = (float*)d_out;
    float* retain = out + FS;
    float* adjs   = retain + (size_t)NB * NN * (NL + 1);
    float* o_l0   = adjs + AS * NL;
    float* o_c    = o_l0 + 1;
    float* o_g    = o_c + NB * NL;

    cudaFuncSetAttribute((const void*)&k_mma<0>, cudaFuncAttributeMaxDynamicSharedMemorySize, SMEM_BYTES);
    cudaFuncSetAttribute((const void*)&k_mma<1>, cudaFuncAttributeMaxDynamicSharedMemorySize, SMEM_BYTES);
    cudaFuncSetAttribute((const void*)&k_mma<2>, cudaFuncAttributeMaxDynamicSharedMemorySize, SMEM_BYTES);

    float *pF, *pAdj;
    __half *pFp, *pWq16, *pWk16, *pMt, *pFt, *paT;
    cudaGetSymbolAddress((void**)&pF, g_F);
    cudaGetSymbolAddress((void**)&pAdj, g_adj);
    cudaGetSymbolAddress((void**)&pFp, g_Fp);
    cudaGetSymbolAddress((void**)&pWq16, g_Wq16);
    cudaGetSymbolAddress((void**)&pWk16, g_Wk16);
    cudaGetSymbolAddress((void**)&pMt, g_Mt);
    cudaGetSymbolAddress((void**)&pFt, g_Ft);
    cudaGetSymbolAddress((void**)&paT, g_aT);

    k_zero<<<1, 128>>>();
    k_init<<<NB, 256>>>(pmask);
    k_cvt<<<(int)(FS / 4 + 255) / 256, 256>>>((const float4*)feature, (__half2*)pFp, (int)(FS / 4));
    k_cvt<<<(int)(NL * DD / 4 + 255) / 256, 256>>>((const float4*)Wq, (__half2*)pWq16, (int)(NL * DD / 4));
    k_cvt<<<(int)(NL * DD / 4 + 255) / 256, 256>>>((const float4*)Wk, (__half2*)pWk16, (int)(NL * DD / 4));

    // Mt[l] = Wk[l] * Wq[l]^T  (fp16 out), batched over layers
    k_mma<0><<<dim3(ND / BN, ND / BM, NL), 256, SMEM_BYTES>>>(
        pWk16, pWq16, nullptr, pMt, ND, ND, ND, ND, DD, DD, 0, DD, nullptr, 0);

    for (int l = 0; l < NL; l++) {
        k_zero_deg<<<64, 256>>>();
        // G = F * Mt[l]^T  (fp16 into g_Ft scratch; consumed by gate before t_ft reuses it)
        k_mma<0><<<dim3(ND / BN, (NB * NN) / BM, 1), 256, SMEM_BYTES>>>(
            pFp, pMt + (size_t)l * DD, nullptr, pFt,
            ND, ND, ND, ND, 0, 0, 0, 0, nullptr, 0);
        // adj = sigmoid(scale * G F^T) * mask (+deg/c/g/l0 + adjT fp16)
        k_mma<1><<<dim3(NN / BN, NN / BM, NB), 256, SMEM_BYTES>>>(
            pFt, pFp, pAdj + (size_t)l * AS, paT,
            ND, ND, ND, NN,
            (size_t)NN * ND, (size_t)NN * ND, (size_t)NN * NN, (size_t)NN * NN, pmask, l);
        k_dis<<<64, 256>>>();
        // Ft = (F * dis[n]) transposed to [d][n], fp16 (overwrites G scratch)
        const float* Fsrc = (l == 0) ? feature : pF + (size_t)(l - 1) * FS;
        t_ft<<<dim3(ND / 32, NN / 32, NB), dim3(32, 8)>>>(Fsrc, pFt);
        // Fout[m,d] = dis[m] * sum_n adjT[m,n]*Ft[d,n]  (fp32 + fp16 for next layer)
        k_mma<2><<<dim3(ND / BN, NN / BM, NB), 256, SMEM_BYTES>>>(
            paT, pFt, pF + (size_t)l * FS, pFp,
            NN, NN, NN, ND,
            (size_t)NN * NN, (size_t)ND * NN, (size_t)NN * ND, (size_t)NN * ND, nullptr, 0);
    }

    k_final<<<NB * NN, 256>>>(feature, projw, projb, out, retain);
    k_repack<<<(int)(AS / 256), 256>>>(adjs);
    k_finalize<<<1, 128>>>(o_l0, o_c, o_g);
}

// round 7
// speedup vs baseline: 2.0155x; 1.0261x over previous
#include <cuda_runtime.h>
#include <cuda_fp16.h>
#include <math.h>
#include <stdint.h>

#define NB 32
#define NN 512
#define ND 768
#define NL 4
#define FS ((size_t)NB * NN * ND)
#define AS ((size_t)NB * NN * NN)
#define DD ((size_t)ND * ND)
#define SCALE_LOGIT 0.03608439182435161f

// GEMM tiling
#define BM 256
#define BN 128
#define BK 32
#define PP 40
#define SM_A 0
#define SM_B (BM * PP)
#define SM_STAGE ((BM + BN) * PP)
#define SMEM_BYTES (2 * SM_STAGE * 2)

// ---------------- static device scratch ----------------
__device__ __align__(16) float g_F[NL][NB * NN * ND];
__device__ __align__(16) float g_adj[NL][NB * NN * NN];
__device__ __align__(16) __half g_Fp[FS];
__device__ __align__(16) __half g_Wq16[NL * DD], g_Wk16[NL * DD];
__device__ __align__(16) __half g_Mt[NL * DD];
__device__ __align__(16) __half g_Ft[NB * ND * NN];
__device__ __align__(16) __half g_aT[NB * NN * NN];
__device__ float g_deg[NL][NB * NN];
__device__ float g_psum[NB];
__device__ float g_fullsum, g_l0, g_cacc[NB * NL], g_gacc[NB * NL];

__device__ __forceinline__ float deg2dis(float d) {
    return (d > 0.f) ? rsqrtf(fmaxf(d, 1e-12f)) : 0.f;
}

// ---------------- small kernels ----------------
__global__ void k_zero() {
    int i = blockIdx.x * 256 + threadIdx.x;
    if (i < NL * NB * NN) ((float*)g_deg)[i] = 0.f;
    if (blockIdx.x == 0) {
        if (threadIdx.x == 0) { g_l0 = 0.f; g_fullsum = 0.f; }
        if (threadIdx.x < NB * NL) { g_cacc[threadIdx.x] = 0.f; g_gacc[threadIdx.x] = 0.f; }
    }
}

__global__ void k_init(const float* __restrict__ pmask) {
    int b = blockIdx.x;
    float s = 0.f;
    for (int i = threadIdx.x; i < NN; i += 256) s += pmask[b * NN + i];
#pragma unroll
    for (int o = 16; o; o >>= 1) s += __shfl_xor_sync(0xffffffffu, s, o);
    __shared__ float sh[8];
    if ((threadIdx.x & 31) == 0) sh[threadIdx.x >> 5] = s;
    __syncthreads();
    if (threadIdx.x == 0) {
        float t = 0.f;
        for (int w = 0; w < 8; w++) t += sh[w];
        g_psum[b] = t;
        atomicAdd(&g_fullsum, t * t);
    }
}

// single fused fp32->fp16 convert for feature / Wq / Wk
__global__ void k_cvt3(const float4* __restrict__ f, const float4* __restrict__ wq,
                       const float4* __restrict__ wk, __half2* __restrict__ hf,
                       __half2* __restrict__ hwq, __half2* __restrict__ hwk) {
    const int NF = (int)(FS / 4), NW = (int)(NL * DD / 4);
    int i = blockIdx.x * 256 + threadIdx.x;
    const float4* src;
    __half2* dst;
    int j;
    if (i < NF) { src = f; dst = hf; j = i; }
    else if (i < NF + NW) { src = wq; dst = hwq; j = i - NF; }
    else if (i < NF + 2 * NW) { src = wk; dst = hwk; j = i - NF - NW; }
    else return;
    float4 v = src[j];
    dst[2 * j]     = __floats2half2_rn(v.x, v.y);
    dst[2 * j + 1] = __floats2half2_rn(v.z, v.w);
}

// Ft[b][d][n] = Fp[b][n][d] * dis(deg[layer][b][n]), fp16 in/out
__global__ void t_ft(const __half* __restrict__ Fp, __half* __restrict__ Ft, int layer) {
    int b = blockIdx.z, d0 = blockIdx.x * 32, n0 = blockIdx.y * 32;
    __shared__ float t[32][33];
    int tx = threadIdx.x, ty = threadIdx.y;
#pragma unroll
    for (int r = 0; r < 32; r += 8) {
        int n = n0 + ty + r;
        float dn = deg2dis(g_deg[layer][b * NN + n]);
        t[ty + r][tx] = __half2float(Fp[(size_t)b * NN * ND + (size_t)n * ND + d0 + tx]) * dn;
    }
    __syncthreads();
#pragma unroll
    for (int r = 0; r < 32; r += 8)
        Ft[(size_t)b * ND * NN + (size_t)(d0 + ty + r) * NN + n0 + tx] = __float2half(t[tx][ty + r]);
}

// ---------------- fp16 NT MMA GEMM with ldmatrix fragments ----------------
__device__ __forceinline__ void mma16816(float* d, const uint32_t* a, uint32_t b0, uint32_t b1) {
    asm volatile(
        "mma.sync.aligned.m16n8k16.row.col.f32.f16.f16.f32 "
        "{%0,%1,%2,%3},{%4,%5,%6,%7},{%8,%9},{%0,%1,%2,%3};\n"
        : "+f"(d[0]), "+f"(d[1]), "+f"(d[2]), "+f"(d[3])
        : "r"(a[0]), "r"(a[1]), "r"(a[2]), "r"(a[3]), "r"(b0), "r"(b1));
}

__device__ __forceinline__ void ldsm4(uint32_t& d0, uint32_t& d1, uint32_t& d2, uint32_t& d3,
                                      uint32_t addr) {
    asm volatile("ldmatrix.sync.aligned.m8n8.x4.shared.b16 {%0,%1,%2,%3}, [%4];\n"
                 : "=r"(d0), "=r"(d1), "=r"(d2), "=r"(d3) : "r"(addr));
}

__device__ __forceinline__ void cpa16(__half* dst, const __half* src) {
    uint32_t d = (uint32_t)__cvta_generic_to_shared(dst);
    asm volatile("cp.async.cg.shared.global [%0], [%1], 16;\n" :: "r"(d), "l"(src));
}

// EPI: 0 = fp16 store, 1 = gate, 2 = prop
template <int EPI>
__global__ void __launch_bounds__(256, 1) k_mma(
    const __half* __restrict__ Ag, const __half* __restrict__ Bg,
    float* __restrict__ C, __half* __restrict__ O,
    int K, int lda, int ldb, int ldc,
    size_t bsA, size_t bsB, size_t bsC, size_t bsO,
    const float* __restrict__ pmask, int layer)
{
    extern __shared__ __align__(16) __half smem[];
    __shared__ float pmr[BM], pmc[BN];
    __shared__ float red[3][8];

    const int bz = blockIdx.z;
    Ag += bz * bsA; Bg += bz * bsB;
    if (C) C += bz * bsC;
    if (O) O += bz * bsO;

    const int tid = threadIdx.x;
    const int m0 = blockIdx.y * BM;
    const int n0 = blockIdx.x * BN;

    if (EPI == 1) {
        pmr[tid] = pmask[bz * NN + m0 + tid];
        if (tid < BN) pmc[tid] = pmask[bz * NN + n0 + tid];
    }

    auto load_stage = [&](int s, int k0) {
        __half* dst = smem + s * SM_STAGE;
#pragma unroll
        for (int i = 0; i < 4; i++) {
            int q = i * 256 + tid, row = q >> 2, c = q & 3;
            cpa16(dst + SM_A + row * PP + c * 8, Ag + (size_t)(m0 + row) * lda + k0 + c * 8);
        }
#pragma unroll
        for (int i = 0; i < 2; i++) {
            int q = i * 256 + tid, row = q >> 2, c = q & 3;
            cpa16(dst + SM_B + row * PP + c * 8, Bg + (size_t)(n0 + row) * ldb + k0 + c * 8);
        }
        asm volatile("cp.async.commit_group;\n");
    };

    float acc[4][8][4];
#pragma unroll
    for (int mi = 0; mi < 4; mi++)
#pragma unroll
        for (int nj = 0; nj < 8; nj++)
#pragma unroll
            for (int q = 0; q < 4; q++) acc[mi][nj][q] = 0.f;

    const int lane = tid & 31;
    const int wid = tid >> 5;
    const int g = lane >> 2, t4 = lane & 3;
    const int wr = (wid & 3) * 64;
    const int wc = (wid >> 2) * 64;

    // ldmatrix lane addressing (halves; *2 for bytes)
    const uint32_t smem32 = (uint32_t)__cvta_generic_to_shared(smem);
    const int aRow = wr + (lane & 15);             // + 16*mi
    const int aKof = (lane >> 4) << 3;
    const int bRow = wc + (lane & 7) + ((lane >> 4) << 3);  // + 16*j
    const int bKof = ((lane >> 3) & 1) << 3;

    load_stage(0, 0);
    const int KT = K / BK;
    for (int kt = 0; kt < KT; kt++) {
        const int s = kt & 1;
        if (kt + 1 < KT) {
            load_stage(s ^ 1, (kt + 1) * BK);
            asm volatile("cp.async.wait_group 1;\n");
        } else {
            asm volatile("cp.async.wait_group 0;\n");
        }
        __syncthreads();

        const uint32_t sA32 = smem32 + (s * SM_STAGE + SM_A) * 2;
        const uint32_t sB32 = smem32 + (s * SM_STAGE + SM_B) * 2;

#pragma unroll
        for (int kk = 0; kk < BK; kk += 16) {
            uint32_t af[4][4], bf[8][2];
#pragma unroll
            for (int mi = 0; mi < 4; mi++)
                ldsm4(af[mi][0], af[mi][1], af[mi][2], af[mi][3],
                      sA32 + ((aRow + 16 * mi) * PP + kk + aKof) * 2);
#pragma unroll
            for (int j = 0; j < 4; j++)
                ldsm4(bf[2 * j][0], bf[2 * j][1], bf[2 * j + 1][0], bf[2 * j + 1][1],
                      sB32 + ((bRow + 16 * j) * PP + kk + bKof) * 2);
#pragma unroll
            for (int nj = 0; nj < 8; nj++)
#pragma unroll
                for (int mi = 0; mi < 4; mi++)
                    mma16816(acc[mi][nj], af[mi], bf[nj][0], bf[nj][1]);
        }
        __syncthreads();
    }

    // ---------------- epilogues ----------------
    if (EPI == 0) {
#pragma unroll
        for (int mi = 0; mi < 4; mi++) {
            const int R = m0 + wr + 16 * mi + g;
#pragma unroll
            for (int nj = 0; nj < 8; nj++) {
                const int Cc = n0 + wc + 8 * nj + 2 * t4;
                *(__half2*)(O + (size_t)R * ldc + Cc) =
                    __floats2half2_rn(acc[mi][nj][0], acc[mi][nj][1]);
                *(__half2*)(O + (size_t)(R + 8) * ldc + Cc) =
                    __floats2half2_rn(acc[mi][nj][2], acc[mi][nj][3]);
            }
        }
    } else if (EPI == 2) {
#pragma unroll
        for (int mi = 0; mi < 4; mi++) {
            const int R = m0 + wr + 16 * mi + g;
            const float s1 = deg2dis(g_deg[layer][bz * NN + R]);
            const float s2 = deg2dis(g_deg[layer][bz * NN + R + 8]);
#pragma unroll
            for (int nj = 0; nj < 8; nj++) {
                const int Cc = n0 + wc + 8 * nj + 2 * t4;
                float v0 = acc[mi][nj][0] * s1, v1 = acc[mi][nj][1] * s1;
                float v2 = acc[mi][nj][2] * s2, v3 = acc[mi][nj][3] * s2;
                size_t i1 = (size_t)R * ldc + Cc, i2 = (size_t)(R + 8) * ldc + Cc;
                *(float2*)(C + i1) = make_float2(v0, v1);
                *(float2*)(C + i2) = make_float2(v2, v3);
                *(__half2*)(O + i1) = __floats2half2_rn(v0, v1);
                *(__half2*)(O + i2) = __floats2half2_rn(v2, v3);
            }
        }
    } else {  // gate
        float l0loc = 0.f, cloc = 0.f, gloc = 0.f;
#pragma unroll
        for (int mi = 0; mi < 4; mi++) {
            const int Rl = wr + 16 * mi + g;
            const int R = m0 + Rl;
            const float pr1 = pmr[Rl], pr2 = pmr[Rl + 8];
            float row1 = 0.f, row2 = 0.f;
#pragma unroll
            for (int nj = 0; nj < 8; nj++) {
                const int Ccl = wc + 8 * nj + 2 * t4;
                const int Cc = n0 + Ccl;
                const float pc0 = pmc[Ccl], pc1 = pmc[Ccl + 1];
                float v00 = (1.f / (1.f + expf(-acc[mi][nj][0] * SCALE_LOGIT))) * pr1 * pc0;
                float v01 = (1.f / (1.f + expf(-acc[mi][nj][1] * SCALE_LOGIT))) * pr1 * pc1;
                float v10 = (1.f / (1.f + expf(-acc[mi][nj][2] * SCALE_LOGIT))) * pr2 * pc0;
                float v11 = (1.f / (1.f + expf(-acc[mi][nj][3] * SCALE_LOGIT))) * pr2 * pc1;
                row1 += v00 + v01;
                row2 += v10 + v11;
                l0loc += v00 + v01 + v10 + v11;
                const bool c0ok = (Cc < NN - 1), c1ok = (Cc + 1 < NN - 1);
                float e1 = (c0ok ? v00 : 0.f) + (c1ok ? v01 : 0.f);
                float e2 = (c0ok ? v10 : 0.f) + (c1ok ? v11 : 0.f);
                if (R == NN - 1) cloc += e1; else gloc += e1;
                if (R + 8 == NN - 1) cloc += e2; else gloc += e2;
                *(float2*)(C + (size_t)R * ldc + Cc) = make_float2(v00, v01);
                *(float2*)(C + (size_t)(R + 8) * ldc + Cc) = make_float2(v10, v11);
                O[(size_t)Cc * NN + R]           = __float2half(v00);
                O[(size_t)(Cc + 1) * NN + R]     = __float2half(v01);
                O[(size_t)Cc * NN + R + 8]       = __float2half(v10);
                O[(size_t)(Cc + 1) * NN + R + 8] = __float2half(v11);
            }
            row1 += __shfl_xor_sync(0xffffffffu, row1, 1);
            row1 += __shfl_xor_sync(0xffffffffu, row1, 2);
            row2 += __shfl_xor_sync(0xffffffffu, row2, 1);
            row2 += __shfl_xor_sync(0xffffffffu, row2, 2);
            if (t4 == 0) {
                atomicAdd(&g_deg[layer][bz * NN + R], row1);
                atomicAdd(&g_deg[layer][bz * NN + R + 8], row2);
            }
        }
#pragma unroll
        for (int o = 16; o; o >>= 1) {
            l0loc += __shfl_xor_sync(0xffffffffu, l0loc, o);
            cloc  += __shfl_xor_sync(0xffffffffu, cloc, o);
            gloc  += __shfl_xor_sync(0xffffffffu, gloc, o);
        }
        if (lane == 0) { red[0][wid] = l0loc; red[1][wid] = cloc; red[2][wid] = gloc; }
        __syncthreads();
        if (tid == 0) {
            float a = 0.f, c = 0.f, gg = 0.f;
            for (int w = 0; w < 8; w++) { a += red[0][w]; c += red[1][w]; gg += red[2][w]; }
            atomicAdd(&g_l0, a);
            atomicAdd(&g_cacc[bz * NL + layer], c);
            atomicAdd(&g_gacc[bz * NL + layer], gg);
        }
    }
}

// ---------------- attention-pool epilogue ----------------
__global__ void __launch_bounds__(256) k_final(
    const float* __restrict__ F0, const float* __restrict__ projw,
    const float* __restrict__ projb, float* __restrict__ out, float* __restrict__ retain)
{
    const int bn = blockIdx.x;
    const float* p0 = F0 + (size_t)bn * ND;
    const float* p1 = g_F[0] + (size_t)bn * ND;
    const float* p2 = g_F[1] + (size_t)bn * ND;
    const float* p3 = g_F[2] + (size_t)bn * ND;
    const float* p4 = g_F[3] + (size_t)bn * ND;
    float d0 = 0.f, d1 = 0.f, d2 = 0.f, d3 = 0.f, d4 = 0.f;
    for (int i = threadIdx.x; i < ND; i += 256) {
        float w = projw[i];
        d0 += p0[i] * w; d1 += p1[i] * w; d2 += p2[i] * w; d3 += p3[i] * w; d4 += p4[i] * w;
    }
#pragma unroll
    for (int o = 16; o; o >>= 1) {
        d0 += __shfl_xor_sync(0xffffffffu, d0, o);
        d1 += __shfl_xor_sync(0xffffffffu, d1, o);
        d2 += __shfl_xor_sync(0xffffffffu, d2, o);
        d3 += __shfl_xor_sync(0xffffffffu, d3, o);
        d4 += __shfl_xor_sync(0xffffffffu, d4, o);
    }
    __shared__ float sh[5][8], r[5];
    const int wid = threadIdx.x >> 5, lane = threadIdx.x & 31;
    if (lane == 0) { sh[0][wid] = d0; sh[1][wid] = d1; sh[2][wid] = d2; sh[3][wid] = d3; sh[4][wid] = d4; }
    __syncthreads();
    if (threadIdx.x < 5) {
        float t = 0.f;
        for (int w = 0; w < 8; w++) t += sh[threadIdx.x][w];
        float rr = 1.f / (1.f + expf(-(t + projb[0])));
        r[threadIdx.x] = rr;
        retain[(size_t)bn * (NL + 1) + threadIdx.x] = rr;
    }
    __syncthreads();
    const float r0 = r[0], r1 = r[1], r2 = r[2], r3 = r[3], r4 = r[4];
    for (int i = threadIdx.x; i < ND; i += 256)
        out[(size_t)bn * ND + i] = r0 * p0[i] + r1 * p1[i] + r2 * p2[i] + r3 * p3[i] + r4 * p4[i];
}

__global__ void k_repack(float* __restrict__ adjs_out) {
    size_t i = (size_t)blockIdx.x * 256 + threadIdx.x;
    ((float4*)adjs_out)[i] = make_float4(g_adj[0][i], g_adj[1][i], g_adj[2][i], g_adj[3][i]);
}

__global__ void k_finalize(float* __restrict__ o_l0, float* __restrict__ o_c, float* __restrict__ o_g) {
    int t = threadIdx.x;
    if (t == 0) *o_l0 = g_l0 / ((g_fullsum + 1e-8f) * (float)NL);
    if (t < NB * NL) {
        int b = t / NL;
        float ps = g_psum[b];
        o_c[t] = g_cacc[t] / ps;
        o_g[t] = g_gacc[t] / (ps * ps);
    }
}

// ---------------- host orchestration ----------------
extern "C" void kernel_launch(void* const* d_in, const int* in_sizes, int n_in,
                              void* d_out, int out_size)
{
    (void)in_sizes; (void)n_in; (void)out_size;
    const float* pmask   = (const float*)d_in[0];
    const float* feature = (const float*)d_in[1];
    const float* Wq      = (const float*)d_in[2];
    const float* Wk      = (const float*)d_in[3];
    const float* projw   = (const float*)d_in[4];
    const float* projb   = (const float*)d_in[5];

    float* out    = (float*)d_out;
    float* retain = out + FS;
    float* adjs   = retain + (size_t)NB * NN * (NL + 1);
    float* o_l0   = adjs + AS * NL;
    float* o_c    = o_l0 + 1;
    float* o_g    = o_c + NB * NL;

    cudaFuncSetAttribute((const void*)&k_mma<0>, cudaFuncAttributeMaxDynamicSharedMemorySize, SMEM_BYTES);
    cudaFuncSetAttribute((const void*)&k_mma<1>, cudaFuncAttributeMaxDynamicSharedMemorySize, SMEM_BYTES);
    cudaFuncSetAttribute((const void*)&k_mma<2>, cudaFuncAttributeMaxDynamicSharedMemorySize, SMEM_BYTES);

    float *pF, *pAdj;
    __half *pFp, *pWq16, *pWk16, *pMt, *pFt, *paT;
    cudaGetSymbolAddress((void**)&pF, g_F);
    cudaGetSymbolAddress((void**)&pAdj, g_adj);
    cudaGetSymbolAddress((void**)&pFp, g_Fp);
    cudaGetSymbolAddress((void**)&pWq16, g_Wq16);
    cudaGetSymbolAddress((void**)&pWk16, g_Wk16);
    cudaGetSymbolAddress((void**)&pMt, g_Mt);
    cudaGetSymbolAddress((void**)&pFt, g_Ft);
    cudaGetSymbolAddress((void**)&paT, g_aT);

    k_zero<<<256, 256>>>();
    k_init<<<NB, 256>>>(pmask);
    {
        int total = (int)(FS / 4) + 2 * (int)(NL * DD / 4);
        k_cvt3<<<(total + 255) / 256, 256>>>(
            (const float4*)feature, (const float4*)Wq, (const float4*)Wk,
            (__half2*)pFp, (__half2*)pWq16, (__half2*)pWk16);
    }

    // Mt[l] = Wk[l] * Wq[l]^T (fp16), batched over layers
    k_mma<0><<<dim3(ND / BN, ND / BM, NL), 256, SMEM_BYTES>>>(
        pWk16, pWq16, nullptr, pMt, ND, ND, ND, ND, DD, DD, 0, DD, nullptr, 0);

    for (int l = 0; l < NL; l++) {
        // G = F * Mt[l]^T (fp16 into g_Ft scratch)
        k_mma<0><<<dim3(ND / BN, (NB * NN) / BM, 1), 256, SMEM_BYTES>>>(
            pFp, pMt + (size_t)l * DD, nullptr, pFt,
            ND, ND, ND, ND, 0, 0, 0, 0, nullptr, 0);
        // adj = sigmoid(scale * G F^T) * mask (+deg/c/g/l0 + adjT fp16)
        k_mma<1><<<dim3(NN / BN, NN / BM, NB), 256, SMEM_BYTES>>>(
            pFt, pFp, pAdj + (size_t)l * AS, paT,
            ND, ND, ND, NN,
            (size_t)NN * ND, (size_t)NN * ND, (size_t)NN * NN, (size_t)NN * NN, pmask, l);
        // Ft = (F * dis[n])^T fp16 (overwrites G scratch); dis folded from deg
        t_ft<<<dim3(ND / 32, NN / 32, NB), dim3(32, 8)>>>(pFp, pFt, l);
        // Fout[m,d] = dis[m] * sum_n adjT[m,n]*Ft[d,n]
        k_mma<2><<<dim3(ND / BN, NN / BM, NB), 256, SMEM_BYTES>>>(
            paT, pFt, pF + (size_t)l * FS, pFp,
            NN, NN, NN, ND,
            (size_t)NN * NN, (size_t)ND * NN, (size_t)NN * ND, (size_t)NN * ND, nullptr, l);
    }

    k_final<<<NB * NN, 256>>>(feature, projw, projb, out, retain);
    k_repack<<<(int)(AS / 256), 256>>>(adjs);
    k_finalize<<<1, 128>>>(o_l0, o_c, o_g);
}

// round 8
// speedup vs baseline: 2.2156x; 1.0993x over previous
#include <cuda_runtime.h>
#include <cuda_fp16.h>
#include <math.h>
#include <stdint.h>

#define NB 32
#define NN 512
#define ND 768
#define NL 4
#define FS ((size_t)NB * NN * ND)
#define AS ((size_t)NB * NN * NN)
#define DD ((size_t)ND * ND)
#define SCALE_LOGIT 0.03608439182435161f

// GEMM tiling: 128x128x32, 256 threads, 2 CTAs/SM
#define BM 128
#define BN 128
#define BK 32
#define PP 40
#define SM_A 0
#define SM_B (BM * PP)
#define SM_STAGE ((BM + BN) * PP)
#define SMEM_BYTES (2 * SM_STAGE * 2)   // 40960 B

// ---------------- static device scratch ----------------
__device__ __align__(16) float g_F[NL][NB * NN * ND];
__device__ __align__(16) float g_adj[NL][NB * NN * NN];
__device__ __align__(16) __half g_Fp[FS];
__device__ __align__(16) __half g_Wq16[NL * DD], g_Wk16[NL * DD];
__device__ __align__(16) __half g_Mt[NL * DD];
__device__ __align__(16) __half g_Ft[NB * ND * NN];
__device__ __align__(16) __half g_aT[NB * NN * NN];
__device__ float g_deg[NL][NB * NN];
__device__ float g_psum[NB];
__device__ float g_fullsum, g_l0, g_cacc[NB * NL], g_gacc[NB * NL];

__device__ __forceinline__ float deg2dis(float d) {
    return (d > 0.f) ? rsqrtf(fmaxf(d, 1e-12f)) : 0.f;
}

// ---------------- small kernels ----------------
__global__ void k_zero() {
    int i = blockIdx.x * 256 + threadIdx.x;
    if (i < NL * NB * NN) ((float*)g_deg)[i] = 0.f;
    if (blockIdx.x == 0) {
        if (threadIdx.x == 0) { g_l0 = 0.f; g_fullsum = 0.f; }
        if (threadIdx.x < NB * NL) { g_cacc[threadIdx.x] = 0.f; g_gacc[threadIdx.x] = 0.f; }
    }
}

__global__ void k_init(const float* __restrict__ pmask) {
    int b = blockIdx.x;
    float s = 0.f;
    for (int i = threadIdx.x; i < NN; i += 256) s += pmask[b * NN + i];
#pragma unroll
    for (int o = 16; o; o >>= 1) s += __shfl_xor_sync(0xffffffffu, s, o);
    __shared__ float sh[8];
    if ((threadIdx.x & 31) == 0) sh[threadIdx.x >> 5] = s;
    __syncthreads();
    if (threadIdx.x == 0) {
        float t = 0.f;
        for (int w = 0; w < 8; w++) t += sh[w];
        g_psum[b] = t;
        atomicAdd(&g_fullsum, t * t);
    }
}

__global__ void k_cvt3(const float4* __restrict__ f, const float4* __restrict__ wq,
                       const float4* __restrict__ wk, __half2* __restrict__ hf,
                       __half2* __restrict__ hwq, __half2* __restrict__ hwk) {
    const int NF = (int)(FS / 4), NW = (int)(NL * DD / 4);
    int i = blockIdx.x * 256 + threadIdx.x;
    const float4* src;
    __half2* dst;
    int j;
    if (i < NF) { src = f; dst = hf; j = i; }
    else if (i < NF + NW) { src = wq; dst = hwq; j = i - NF; }
    else if (i < NF + 2 * NW) { src = wk; dst = hwk; j = i - NF - NW; }
    else return;
    float4 v = src[j];
    dst[2 * j]     = __floats2half2_rn(v.x, v.y);
    dst[2 * j + 1] = __floats2half2_rn(v.z, v.w);
}

// Ft[b][d][n] = Fp[b][n][d] * dis(deg[layer][b][n])
__global__ void t_ft(const __half* __restrict__ Fp, __half* __restrict__ Ft, int layer) {
    int b = blockIdx.z, d0 = blockIdx.x * 32, n0 = blockIdx.y * 32;
    __shared__ float t[32][33];
    int tx = threadIdx.x, ty = threadIdx.y;
#pragma unroll
    for (int r = 0; r < 32; r += 8) {
        int n = n0 + ty + r;
        float dn = deg2dis(g_deg[layer][b * NN + n]);
        t[ty + r][tx] = __half2float(Fp[(size_t)b * NN * ND + (size_t)n * ND + d0 + tx]) * dn;
    }
    __syncthreads();
#pragma unroll
    for (int r = 0; r < 32; r += 8)
        Ft[(size_t)b * ND * NN + (size_t)(d0 + ty + r) * NN + n0 + tx] = __float2half(t[tx][ty + r]);
}

// ---------------- fp16 NT MMA GEMM, 2 CTAs/SM ----------------
__device__ __forceinline__ void mma16816(float* d, const uint32_t* a, uint32_t b0, uint32_t b1) {
    asm volatile(
        "mma.sync.aligned.m16n8k16.row.col.f32.f16.f16.f32 "
        "{%0,%1,%2,%3},{%4,%5,%6,%7},{%8,%9},{%0,%1,%2,%3};\n"
        : "+f"(d[0]), "+f"(d[1]), "+f"(d[2]), "+f"(d[3])
        : "r"(a[0]), "r"(a[1]), "r"(a[2]), "r"(a[3]), "r"(b0), "r"(b1));
}

__device__ __forceinline__ void ldsm4(uint32_t& d0, uint32_t& d1, uint32_t& d2, uint32_t& d3,
                                      uint32_t addr) {
    asm volatile("ldmatrix.sync.aligned.m8n8.x4.shared.b16 {%0,%1,%2,%3}, [%4];\n"
                 : "=r"(d0), "=r"(d1), "=r"(d2), "=r"(d3) : "r"(addr));
}

__device__ __forceinline__ void cpa16(__half* dst, const __half* src) {
    uint32_t d = (uint32_t)__cvta_generic_to_shared(dst);
    asm volatile("cp.async.cg.shared.global [%0], [%1], 16;\n" :: "r"(d), "l"(src));
}

// EPI: 0 = fp16 store, 1 = gate, 2 = prop
template <int EPI>
__global__ void __launch_bounds__(256, 2) k_mma(
    const __half* __restrict__ Ag, const __half* __restrict__ Bg,
    float* __restrict__ C, __half* __restrict__ O,
    int K, int lda, int ldb, int ldc,
    size_t bsA, size_t bsB, size_t bsC, size_t bsO,
    const float* __restrict__ pmask, int layer)
{
    extern __shared__ __align__(16) __half smem[];
    __shared__ float pmr[BM], pmc[BN];
    __shared__ float red[3][8];

    const int bz = blockIdx.z;
    Ag += bz * bsA; Bg += bz * bsB;
    if (C) C += bz * bsC;
    if (O) O += bz * bsO;

    const int tid = threadIdx.x;
    const int m0 = blockIdx.y * BM;
    const int n0 = blockIdx.x * BN;

    if (EPI == 1) {
        if (tid < BM) pmr[tid] = pmask[bz * NN + m0 + tid];
        else          pmc[tid - BM] = pmask[bz * NN + n0 + (tid - BM)];
    }

    auto load_stage = [&](int s, int k0) {
        __half* dst = smem + s * SM_STAGE;
#pragma unroll
        for (int i = 0; i < 2; i++) {
            int q = i * 256 + tid, row = q >> 2, c = q & 3;
            cpa16(dst + SM_A + row * PP + c * 8, Ag + (size_t)(m0 + row) * lda + k0 + c * 8);
        }
#pragma unroll
        for (int i = 0; i < 2; i++) {
            int q = i * 256 + tid, row = q >> 2, c = q & 3;
            cpa16(dst + SM_B + row * PP + c * 8, Bg + (size_t)(n0 + row) * ldb + k0 + c * 8);
        }
        asm volatile("cp.async.commit_group;\n");
    };

    float acc[2][8][4];
#pragma unroll
    for (int mi = 0; mi < 2; mi++)
#pragma unroll
        for (int nj = 0; nj < 8; nj++)
#pragma unroll
            for (int q = 0; q < 4; q++) acc[mi][nj][q] = 0.f;

    const int lane = tid & 31;
    const int wid = tid >> 5;
    const int g = lane >> 2, t4 = lane & 3;
    const int wr = (wid & 3) * 32;   // 4 warp-rows x 32
    const int wc = (wid >> 2) * 64;  // 2 warp-cols x 64

    const uint32_t smem32 = (uint32_t)__cvta_generic_to_shared(smem);
    const int aRow = wr + (lane & 15);
    const int aKof = (lane >> 4) << 3;
    const int bRow = wc + (lane & 7) + ((lane >> 4) << 3);
    const int bKof = ((lane >> 3) & 1) << 3;

    load_stage(0, 0);
    const int KT = K / BK;
    for (int kt = 0; kt < KT; kt++) {
        const int s = kt & 1;
        if (kt + 1 < KT) {
            load_stage(s ^ 1, (kt + 1) * BK);
            asm volatile("cp.async.wait_group 1;\n");
        } else {
            asm volatile("cp.async.wait_group 0;\n");
        }
        __syncthreads();

        const uint32_t sA32 = smem32 + (s * SM_STAGE + SM_A) * 2;
        const uint32_t sB32 = smem32 + (s * SM_STAGE + SM_B) * 2;

#pragma unroll
        for (int kk = 0; kk < BK; kk += 16) {
            uint32_t af[2][4], bf[8][2];
#pragma unroll
            for (int mi = 0; mi < 2; mi++)
                ldsm4(af[mi][0], af[mi][1], af[mi][2], af[mi][3],
                      sA32 + ((aRow + 16 * mi) * PP + kk + aKof) * 2);
#pragma unroll
            for (int j = 0; j < 4; j++)
                ldsm4(bf[2 * j][0], bf[2 * j][1], bf[2 * j + 1][0], bf[2 * j + 1][1],
                      sB32 + ((bRow + 16 * j) * PP + kk + bKof) * 2);
#pragma unroll
            for (int nj = 0; nj < 8; nj++)
#pragma unroll
                for (int mi = 0; mi < 2; mi++)
                    mma16816(acc[mi][nj], af[mi], bf[nj][0], bf[nj][1]);
        }
        __syncthreads();
    }

    // ---------------- epilogues ----------------
    if (EPI == 0) {
#pragma unroll
        for (int mi = 0; mi < 2; mi++) {
            const int R = m0 + wr + 16 * mi + g;
#pragma unroll
            for (int nj = 0; nj < 8; nj++) {
                const int Cc = n0 + wc + 8 * nj + 2 * t4;
                *(__half2*)(O + (size_t)R * ldc + Cc) =
                    __floats2half2_rn(acc[mi][nj][0], acc[mi][nj][1]);
                *(__half2*)(O + (size_t)(R + 8) * ldc + Cc) =
                    __floats2half2_rn(acc[mi][nj][2], acc[mi][nj][3]);
            }
        }
    } else if (EPI == 2) {
#pragma unroll
        for (int mi = 0; mi < 2; mi++) {
            const int R = m0 + wr + 16 * mi + g;
            const float s1 = deg2dis(g_deg[layer][bz * NN + R]);
            const float s2 = deg2dis(g_deg[layer][bz * NN + R + 8]);
#pragma unroll
            for (int nj = 0; nj < 8; nj++) {
                const int Cc = n0 + wc + 8 * nj + 2 * t4;
                float v0 = acc[mi][nj][0] * s1, v1 = acc[mi][nj][1] * s1;
                float v2 = acc[mi][nj][2] * s2, v3 = acc[mi][nj][3] * s2;
                size_t i1 = (size_t)R * ldc + Cc, i2 = (size_t)(R + 8) * ldc + Cc;
                *(float2*)(C + i1) = make_float2(v0, v1);
                *(float2*)(C + i2) = make_float2(v2, v3);
                *(__half2*)(O + i1) = __floats2half2_rn(v0, v1);
                *(__half2*)(O + i2) = __floats2half2_rn(v2, v3);
            }
        }
    } else {  // gate
        float l0loc = 0.f, cloc = 0.f, gloc = 0.f;
#pragma unroll
        for (int mi = 0; mi < 2; mi++) {
            const int Rl = wr + 16 * mi + g;
            const int R = m0 + Rl;
            const float pr1 = pmr[Rl], pr2 = pmr[Rl + 8];
            float row1 = 0.f, row2 = 0.f;
#pragma unroll
            for (int nj = 0; nj < 8; nj++) {
                const int Ccl = wc + 8 * nj + 2 * t4;
                const int Cc = n0 + Ccl;
                const float pc0 = pmc[Ccl], pc1 = pmc[Ccl + 1];
                float v00 = (1.f / (1.f + expf(-acc[mi][nj][0] * SCALE_LOGIT))) * pr1 * pc0;
                float v01 = (1.f / (1.f + expf(-acc[mi][nj][1] * SCALE_LOGIT))) * pr1 * pc1;
                float v10 = (1.f / (1.f + expf(-acc[mi][nj][2] * SCALE_LOGIT))) * pr2 * pc0;
                float v11 = (1.f / (1.f + expf(-acc[mi][nj][3] * SCALE_LOGIT))) * pr2 * pc1;
                row1 += v00 + v01;
                row2 += v10 + v11;
                l0loc += v00 + v01 + v10 + v11;
                const bool c0ok = (Cc < NN - 1), c1ok = (Cc + 1 < NN - 1);
                float e1 = (c0ok ? v00 : 0.f) + (c1ok ? v01 : 0.f);
                float e2 = (c0ok ? v10 : 0.f) + (c1ok ? v11 : 0.f);
                if (R == NN - 1) cloc += e1; else gloc += e1;
                if (R + 8 == NN - 1) cloc += e2; else gloc += e2;
                *(float2*)(C + (size_t)R * ldc + Cc) = make_float2(v00, v01);
                *(float2*)(C + (size_t)(R + 8) * ldc + Cc) = make_float2(v10, v11);
                O[(size_t)Cc * NN + R]           = __float2half(v00);
                O[(size_t)(Cc + 1) * NN + R]     = __float2half(v01);
                O[(size_t)Cc * NN + R + 8]       = __float2half(v10);
                O[(size_t)(Cc + 1) * NN + R + 8] = __float2half(v11);
            }
            row1 += __shfl_xor_sync(0xffffffffu, row1, 1);
            row1 += __shfl_xor_sync(0xffffffffu, row1, 2);
            row2 += __shfl_xor_sync(0xffffffffu, row2, 1);
            row2 += __shfl_xor_sync(0xffffffffu, row2, 2);
            if (t4 == 0) {
                atomicAdd(&g_deg[layer][bz * NN + R], row1);
                atomicAdd(&g_deg[layer][bz * NN + R + 8], row2);
            }
        }
#pragma unroll
        for (int o = 16; o; o >>= 1) {
            l0loc += __shfl_xor_sync(0xffffffffu, l0loc, o);
            cloc  += __shfl_xor_sync(0xffffffffu, cloc, o);
            gloc  += __shfl_xor_sync(0xffffffffu, gloc, o);
        }
        if (lane == 0) { red[0][wid] = l0loc; red[1][wid] = cloc; red[2][wid] = gloc; }
        __syncthreads();
        if (tid == 0) {
            float a = 0.f, c = 0.f, gg = 0.f;
            for (int w = 0; w < 8; w++) { a += red[0][w]; c += red[1][w]; gg += red[2][w]; }
            atomicAdd(&g_l0, a);
            atomicAdd(&g_cacc[bz * NL + layer], c);
            atomicAdd(&g_gacc[bz * NL + layer], gg);
        }
    }
}

// ---------------- attention-pool epilogue ----------------
__global__ void __launch_bounds__(256) k_final(
    const float* __restrict__ F0, const float* __restrict__ projw,
    const float* __restrict__ projb, float* __restrict__ out, float* __restrict__ retain)
{
    const int bn = blockIdx.x;
    const float* p0 = F0 + (size_t)bn * ND;
    const float* p1 = g_F[0] + (size_t)bn * ND;
    const float* p2 = g_F[1] + (size_t)bn * ND;
    const float* p3 = g_F[2] + (size_t)bn * ND;
    const float* p4 = g_F[3] + (size_t)bn * ND;
    float d0 = 0.f, d1 = 0.f, d2 = 0.f, d3 = 0.f, d4 = 0.f;
    for (int i = threadIdx.x; i < ND; i += 256) {
        float w = projw[i];
        d0 += p0[i] * w; d1 += p1[i] * w; d2 += p2[i] * w; d3 += p3[i] * w; d4 += p4[i] * w;
    }
#pragma unroll
    for (int o = 16; o; o >>= 1) {
        d0 += __shfl_xor_sync(0xffffffffu, d0, o);
        d1 += __shfl_xor_sync(0xffffffffu, d1, o);
        d2 += __shfl_xor_sync(0xffffffffu, d2, o);
        d3 += __shfl_xor_sync(0xffffffffu, d3, o);
        d4 += __shfl_xor_sync(0xffffffffu, d4, o);
    }
    __shared__ float sh[5][8], r[5];
    const int wid = threadIdx.x >> 5, lane = threadIdx.x & 31;
    if (lane == 0) { sh[0][wid] = d0; sh[1][wid] = d1; sh[2][wid] = d2; sh[3][wid] = d3; sh[4][wid] = d4; }
    __syncthreads();
    if (threadIdx.x < 5) {
        float t = 0.f;
        for (int w = 0; w < 8; w++) t += sh[threadIdx.x][w];
        float rr = 1.f / (1.f + expf(-(t + projb[0])));
        r[threadIdx.x] = rr;
        retain[(size_t)bn * (NL + 1) + threadIdx.x] = rr;
    }
    __syncthreads();
    const float r0 = r[0], r1 = r[1], r2 = r[2], r3 = r[3], r4 = r[4];
    for (int i = threadIdx.x; i < ND; i += 256)
        out[(size_t)bn * ND + i] = r0 * p0[i] + r1 * p1[i] + r2 * p2[i] + r3 * p3[i] + r4 * p4[i];
}

__global__ void k_repack(float* __restrict__ adjs_out) {
    size_t i = (size_t)blockIdx.x * 256 + threadIdx.x;
    ((float4*)adjs_out)[i] = make_float4(g_adj[0][i], g_adj[1][i], g_adj[2][i], g_adj[3][i]);
}

__global__ void k_finalize(float* __restrict__ o_l0, float* __restrict__ o_c, float* __restrict__ o_g) {
    int t = threadIdx.x;
    if (t == 0) *o_l0 = g_l0 / ((g_fullsum + 1e-8f) * (float)NL);
    if (t < NB * NL) {
        int b = t / NL;
        float ps = g_psum[b];
        o_c[t] = g_cacc[t] / ps;
        o_g[t] = g_gacc[t] / (ps * ps);
    }
}

// ---------------- host orchestration ----------------
extern "C" void kernel_launch(void* const* d_in, const int* in_sizes, int n_in,
                              void* d_out, int out_size)
{
    (void)in_sizes; (void)n_in; (void)out_size;
    const float* pmask   = (const float*)d_in[0];
    const float* feature = (const float*)d_in[1];
    const float* Wq      = (const float*)d_in[2];
    const float* Wk      = (const float*)d_in[3];
    const float* projw   = (const float*)d_in[4];
    const float* projb   = (const float*)d_in[5];

    float* out    = (float*)d_out;
    float* retain = out + FS;
    float* adjs   = retain + (size_t)NB * NN * (NL + 1);
    float* o_l0   = adjs + AS * NL;
    float* o_c    = o_l0 + 1;
    float* o_g    = o_c + NB * NL;

    float *pF, *pAdj;
    __half *pFp, *pWq16, *pWk16, *pMt, *pFt, *paT;
    cudaGetSymbolAddress((void**)&pF, g_F);
    cudaGetSymbolAddress((void**)&pAdj, g_adj);
    cudaGetSymbolAddress((void**)&pFp, g_Fp);
    cudaGetSymbolAddress((void**)&pWq16, g_Wq16);
    cudaGetSymbolAddress((void**)&pWk16, g_Wk16);
    cudaGetSymbolAddress((void**)&pMt, g_Mt);
    cudaGetSymbolAddress((void**)&pFt, g_Ft);
    cudaGetSymbolAddress((void**)&paT, g_aT);

    k_zero<<<256, 256>>>();
    k_init<<<NB, 256>>>(pmask);
    {
        int total = (int)(FS / 4) + 2 * (int)(NL * DD / 4);
        k_cvt3<<<(total + 255) / 256, 256>>>(
            (const float4*)feature, (const float4*)Wq, (const float4*)Wk,
            (__half2*)pFp, (__half2*)pWq16, (__half2*)pWk16);
    }

    // Mt[l] = Wk[l] * Wq[l]^T (fp16), batched over layers
    k_mma<0><<<dim3(ND / BN, ND / BM, NL), 256, SMEM_BYTES>>>(
        pWk16, pWq16, nullptr, pMt, ND, ND, ND, ND, DD, DD, 0, DD, nullptr, 0);

    for (int l = 0; l < NL; l++) {
        // G = F * Mt[l]^T (fp16 into g_Ft scratch)
        k_mma<0><<<dim3(ND / BN, (NB * NN) / BM, 1), 256, SMEM_BYTES>>>(
            pFp, pMt + (size_t)l * DD, nullptr, pFt,
            ND, ND, ND, ND, 0, 0, 0, 0, nullptr, 0);
        // adj = sigmoid(scale * G F^T) * mask (+deg/c/g/l0 + adjT fp16)
        k_mma<1><<<dim3(NN / BN, NN / BM, NB), 256, SMEM_BYTES>>>(
            pFt, pFp, pAdj + (size_t)l * AS, paT,
            ND, ND, ND, NN,
            (size_t)NN * ND, (size_t)NN * ND, (size_t)NN * NN, (size_t)NN * NN, pmask, l);
        // Ft = (F * dis[n])^T fp16 (overwrites G scratch)
        t_ft<<<dim3(ND / 32, NN / 32, NB), dim3(32, 8)>>>(pFp, pFt, l);
        // Fout[m,d] = dis[m] * sum_n adjT[m,n]*Ft[d,n]
        k_mma<2><<<dim3(ND / BN, NN / BM, NB), 256, SMEM_BYTES>>>(
            paT, pFt, pF + (size_t)l * FS, pFp,
            NN, NN, NN, ND,
            (size_t)NN * NN, (size_t)ND * NN, (size_t)NN * ND, (size_t)NN * ND, nullptr, l);
    }

    k_final<<<NB * NN, 256>>>(feature, projw, projb, out, retain);
    k_repack<<<(int)(AS / 256), 256>>>(adjs);
    k_finalize<<<1, 128>>>(o_l0, o_c, o_g);
}

// round 9
// speedup vs baseline: 2.2500x; 1.0155x over previous
#include <cuda_runtime.h>
#include <cuda_fp16.h>
#include <math.h>
#include <stdint.h>

#define NB 32
#define NN 512
#define ND 768
#define NL 4
#define FS ((size_t)NB * NN * ND)
#define AS ((size_t)NB * NN * NN)
#define DD ((size_t)ND * ND)
#define SCALE_LOGIT 0.03608439182435161f

// GEMM tiling: 128x128x32, 256 threads, 2 CTAs/SM, 3-stage pipeline
#define BM 128
#define BN 128
#define BK 32
#define PP 40
#define SM_A 0
#define SM_B (BM * PP)
#define SM_STAGE ((BM + BN) * PP)        // 10240 halves = 20480 B
#define SMEM_BYTES (3 * SM_STAGE * 2)    // 61440 B

// ---------------- static device scratch ----------------
__device__ __align__(16) float g_F[NL][NB * NN * ND];
__device__ __align__(16) float g_adj[NL][NB * NN * NN];
__device__ __align__(16) __half g_Fp[FS];
__device__ __align__(16) __half g_Wq16[NL * DD], g_Wk16[NL * DD];
__device__ __align__(16) __half g_Mt[NL * DD];
__device__ __align__(16) __half g_Ft[NB * ND * NN];
__device__ __align__(16) __half g_aT[NB * NN * NN];
__device__ float g_deg[NL][NB * NN];
__device__ float g_psum[NB];
__device__ float g_fullsum, g_l0, g_cacc[NB * NL], g_gacc[NB * NL];

__device__ __forceinline__ float deg2dis(float d) {
    return (d > 0.f) ? rsqrtf(fmaxf(d, 1e-12f)) : 0.f;
}

// ---------------- small kernels ----------------
__global__ void k_zero() {
    int i = blockIdx.x * 256 + threadIdx.x;
    if (i < NL * NB * NN) ((float*)g_deg)[i] = 0.f;
    if (blockIdx.x == 0) {
        if (threadIdx.x == 0) { g_l0 = 0.f; g_fullsum = 0.f; }
        if (threadIdx.x < NB * NL) { g_cacc[threadIdx.x] = 0.f; g_gacc[threadIdx.x] = 0.f; }
    }
}

__global__ void k_init(const float* __restrict__ pmask) {
    int b = blockIdx.x;
    float s = 0.f;
    for (int i = threadIdx.x; i < NN; i += 256) s += pmask[b * NN + i];
#pragma unroll
    for (int o = 16; o; o >>= 1) s += __shfl_xor_sync(0xffffffffu, s, o);
    __shared__ float sh[8];
    if ((threadIdx.x & 31) == 0) sh[threadIdx.x >> 5] = s;
    __syncthreads();
    if (threadIdx.x == 0) {
        float t = 0.f;
        for (int w = 0; w < 8; w++) t += sh[w];
        g_psum[b] = t;
        atomicAdd(&g_fullsum, t * t);
    }
}

__global__ void k_cvt3(const float4* __restrict__ f, const float4* __restrict__ wq,
                       const float4* __restrict__ wk, __half2* __restrict__ hf,
                       __half2* __restrict__ hwq, __half2* __restrict__ hwk) {
    const int NF = (int)(FS / 4), NW = (int)(NL * DD / 4);
    int i = blockIdx.x * 256 + threadIdx.x;
    const float4* src;
    __half2* dst;
    int j;
    if (i < NF) { src = f; dst = hf; j = i; }
    else if (i < NF + NW) { src = wq; dst = hwq; j = i - NF; }
    else if (i < NF + 2 * NW) { src = wk; dst = hwk; j = i - NF - NW; }
    else return;
    float4 v = src[j];
    dst[2 * j]     = __floats2half2_rn(v.x, v.y);
    dst[2 * j + 1] = __floats2half2_rn(v.z, v.w);
}

// Ft[b][d][n] = Fp[b][n][d] * dis(deg[layer][b][n])
__global__ void t_ft(const __half* __restrict__ Fp, __half* __restrict__ Ft, int layer) {
    int b = blockIdx.z, d0 = blockIdx.x * 32, n0 = blockIdx.y * 32;
    __shared__ float t[32][33];
    int tx = threadIdx.x, ty = threadIdx.y;
#pragma unroll
    for (int r = 0; r < 32; r += 8) {
        int n = n0 + ty + r;
        float dn = deg2dis(g_deg[layer][b * NN + n]);
        t[ty + r][tx] = __half2float(Fp[(size_t)b * NN * ND + (size_t)n * ND + d0 + tx]) * dn;
    }
    __syncthreads();
#pragma unroll
    for (int r = 0; r < 32; r += 8)
        Ft[(size_t)b * ND * NN + (size_t)(d0 + ty + r) * NN + n0 + tx] = __float2half(t[tx][ty + r]);
}

// ---------------- fp16 NT MMA GEMM, 3-stage pipeline, 2 CTAs/SM ----------------
__device__ __forceinline__ void mma16816(float* d, const uint32_t* a, uint32_t b0, uint32_t b1) {
    asm volatile(
        "mma.sync.aligned.m16n8k16.row.col.f32.f16.f16.f32 "
        "{%0,%1,%2,%3},{%4,%5,%6,%7},{%8,%9},{%0,%1,%2,%3};\n"
        : "+f"(d[0]), "+f"(d[1]), "+f"(d[2]), "+f"(d[3])
        : "r"(a[0]), "r"(a[1]), "r"(a[2]), "r"(a[3]), "r"(b0), "r"(b1));
}

__device__ __forceinline__ void ldsm4(uint32_t& d0, uint32_t& d1, uint32_t& d2, uint32_t& d3,
                                      uint32_t addr) {
    asm volatile("ldmatrix.sync.aligned.m8n8.x4.shared.b16 {%0,%1,%2,%3}, [%4];\n"
                 : "=r"(d0), "=r"(d1), "=r"(d2), "=r"(d3) : "r"(addr));
}

__device__ __forceinline__ void cpa16(__half* dst, const __half* src) {
    uint32_t d = (uint32_t)__cvta_generic_to_shared(dst);
    asm volatile("cp.async.cg.shared.global [%0], [%1], 16;\n" :: "r"(d), "l"(src));
}

// EPI: 0 = fp16 store, 1 = gate, 2 = prop
template <int EPI>
__global__ void __launch_bounds__(256, 2) k_mma(
    const __half* __restrict__ Ag, const __half* __restrict__ Bg,
    float* __restrict__ C, __half* __restrict__ O,
    int K, int lda, int ldb, int ldc,
    size_t bsA, size_t bsB, size_t bsC, size_t bsO,
    const float* __restrict__ pmask, int layer)
{
    extern __shared__ __align__(16) __half smem[];
    __shared__ float pmr[BM], pmc[BN];
    __shared__ float red[3][8];

    const int bz = blockIdx.z;
    Ag += bz * bsA; Bg += bz * bsB;
    if (C) C += bz * bsC;
    if (O) O += bz * bsO;

    const int tid = threadIdx.x;
    const int m0 = blockIdx.y * BM;
    const int n0 = blockIdx.x * BN;

    if (EPI == 1) {
        if (tid < BM) pmr[tid] = pmask[bz * NN + m0 + tid];
        else          pmc[tid - BM] = pmask[bz * NN + n0 + (tid - BM)];
    }

    auto load_stage = [&](int s, int k0) {
        __half* dst = smem + s * SM_STAGE;
#pragma unroll
        for (int i = 0; i < 2; i++) {
            int q = i * 256 + tid, row = q >> 2, c = q & 3;
            cpa16(dst + SM_A + row * PP + c * 8, Ag + (size_t)(m0 + row) * lda + k0 + c * 8);
        }
#pragma unroll
        for (int i = 0; i < 2; i++) {
            int q = i * 256 + tid, row = q >> 2, c = q & 3;
            cpa16(dst + SM_B + row * PP + c * 8, Bg + (size_t)(n0 + row) * ldb + k0 + c * 8);
        }
        asm volatile("cp.async.commit_group;\n");
    };

    float acc[2][8][4];
#pragma unroll
    for (int mi = 0; mi < 2; mi++)
#pragma unroll
        for (int nj = 0; nj < 8; nj++)
#pragma unroll
            for (int q = 0; q < 4; q++) acc[mi][nj][q] = 0.f;

    const int lane = tid & 31;
    const int wid = tid >> 5;
    const int g = lane >> 2, t4 = lane & 3;
    const int wr = (wid & 3) * 32;
    const int wc = (wid >> 2) * 64;

    const uint32_t smem32 = (uint32_t)__cvta_generic_to_shared(smem);
    const int aRow = wr + (lane & 15);
    const int aKof = (lane >> 4) << 3;
    const int bRow = wc + (lane & 7) + ((lane >> 4) << 3);
    const int bKof = ((lane >> 3) & 1) << 3;

    const int KT = K / BK;
    load_stage(0, 0);
    load_stage(1, BK);

    for (int kt = 0; kt < KT; kt++) {
        int s = kt % 3;
        if (kt + 1 < KT) {
            asm volatile("cp.async.wait_group 1;\n");
        } else {
            asm volatile("cp.async.wait_group 0;\n");
        }
        __syncthreads();
        if (kt + 2 < KT) load_stage((kt + 2) % 3, (kt + 2) * BK);

        const uint32_t sA32 = smem32 + (s * SM_STAGE + SM_A) * 2;
        const uint32_t sB32 = smem32 + (s * SM_STAGE + SM_B) * 2;

#pragma unroll
        for (int kk = 0; kk < BK; kk += 16) {
            uint32_t af[2][4], bf[8][2];
#pragma unroll
            for (int mi = 0; mi < 2; mi++)
                ldsm4(af[mi][0], af[mi][1], af[mi][2], af[mi][3],
                      sA32 + ((aRow + 16 * mi) * PP + kk + aKof) * 2);
#pragma unroll
            for (int j = 0; j < 4; j++)
                ldsm4(bf[2 * j][0], bf[2 * j][1], bf[2 * j + 1][0], bf[2 * j + 1][1],
                      sB32 + ((bRow + 16 * j) * PP + kk + bKof) * 2);
#pragma unroll
            for (int nj = 0; nj < 8; nj++)
#pragma unroll
                for (int mi = 0; mi < 2; mi++)
                    mma16816(acc[mi][nj], af[mi], bf[nj][0], bf[nj][1]);
        }
    }

    // ---------------- epilogues ----------------
    if (EPI == 0) {
#pragma unroll
        for (int mi = 0; mi < 2; mi++) {
            const int R = m0 + wr + 16 * mi + g;
#pragma unroll
            for (int nj = 0; nj < 8; nj++) {
                const int Cc = n0 + wc + 8 * nj + 2 * t4;
                *(__half2*)(O + (size_t)R * ldc + Cc) =
                    __floats2half2_rn(acc[mi][nj][0], acc[mi][nj][1]);
                *(__half2*)(O + (size_t)(R + 8) * ldc + Cc) =
                    __floats2half2_rn(acc[mi][nj][2], acc[mi][nj][3]);
            }
        }
    } else if (EPI == 2) {
#pragma unroll
        for (int mi = 0; mi < 2; mi++) {
            const int R = m0 + wr + 16 * mi + g;
            const float s1 = deg2dis(g_deg[layer][bz * NN + R]);
            const float s2 = deg2dis(g_deg[layer][bz * NN + R + 8]);
#pragma unroll
            for (int nj = 0; nj < 8; nj++) {
                const int Cc = n0 + wc + 8 * nj + 2 * t4;
                float v0 = acc[mi][nj][0] * s1, v1 = acc[mi][nj][1] * s1;
                float v2 = acc[mi][nj][2] * s2, v3 = acc[mi][nj][3] * s2;
                size_t i1 = (size_t)R * ldc + Cc, i2 = (size_t)(R + 8) * ldc + Cc;
                *(float2*)(C + i1) = make_float2(v0, v1);
                *(float2*)(C + i2) = make_float2(v2, v3);
                *(__half2*)(O + i1) = __floats2half2_rn(v0, v1);
                *(__half2*)(O + i2) = __floats2half2_rn(v2, v3);
            }
        }
    } else {  // gate
        float l0loc = 0.f, cloc = 0.f, gloc = 0.f;
#pragma unroll
        for (int mi = 0; mi < 2; mi++) {
            const int Rl = wr + 16 * mi + g;
            const int R = m0 + Rl;
            const float pr1 = pmr[Rl], pr2 = pmr[Rl + 8];
            float row1 = 0.f, row2 = 0.f;
#pragma unroll
            for (int nj = 0; nj < 8; nj++) {
                const int Ccl = wc + 8 * nj + 2 * t4;
                const int Cc = n0 + Ccl;
                const float pc0 = pmc[Ccl], pc1 = pmc[Ccl + 1];
                float v00 = (1.f / (1.f + expf(-acc[mi][nj][0] * SCALE_LOGIT))) * pr1 * pc0;
                float v01 = (1.f / (1.f + expf(-acc[mi][nj][1] * SCALE_LOGIT))) * pr1 * pc1;
                float v10 = (1.f / (1.f + expf(-acc[mi][nj][2] * SCALE_LOGIT))) * pr2 * pc0;
                float v11 = (1.f / (1.f + expf(-acc[mi][nj][3] * SCALE_LOGIT))) * pr2 * pc1;
                row1 += v00 + v01;
                row2 += v10 + v11;
                l0loc += v00 + v01 + v10 + v11;
                const bool c0ok = (Cc < NN - 1), c1ok = (Cc + 1 < NN - 1);
                float e1 = (c0ok ? v00 : 0.f) + (c1ok ? v01 : 0.f);
                float e2 = (c0ok ? v10 : 0.f) + (c1ok ? v11 : 0.f);
                if (R == NN - 1) cloc += e1; else gloc += e1;
                if (R + 8 == NN - 1) cloc += e2; else gloc += e2;
                *(float2*)(C + (size_t)R * ldc + Cc) = make_float2(v00, v01);
                *(float2*)(C + (size_t)(R + 8) * ldc + Cc) = make_float2(v10, v11);
                O[(size_t)Cc * NN + R]           = __float2half(v00);
                O[(size_t)(Cc + 1) * NN + R]     = __float2half(v01);
                O[(size_t)Cc * NN + R + 8]       = __float2half(v10);
                O[(size_t)(Cc + 1) * NN + R + 8] = __float2half(v11);
            }
            row1 += __shfl_xor_sync(0xffffffffu, row1, 1);
            row1 += __shfl_xor_sync(0xffffffffu, row1, 2);
            row2 += __shfl_xor_sync(0xffffffffu, row2, 1);
            row2 += __shfl_xor_sync(0xffffffffu, row2, 2);
            if (t4 == 0) {
                atomicAdd(&g_deg[layer][bz * NN + R], row1);
                atomicAdd(&g_deg[layer][bz * NN + R + 8], row2);
            }
        }
#pragma unroll
        for (int o = 16; o; o >>= 1) {
            l0loc += __shfl_xor_sync(0xffffffffu, l0loc, o);
            cloc  += __shfl_xor_sync(0xffffffffu, cloc, o);
            gloc  += __shfl_xor_sync(0xffffffffu, gloc, o);
        }
        if (lane == 0) { red[0][wid] = l0loc; red[1][wid] = cloc; red[2][wid] = gloc; }
        __syncthreads();
        if (tid == 0) {
            float a = 0.f, c = 0.f, gg = 0.f;
            for (int w = 0; w < 8; w++) { a += red[0][w]; c += red[1][w]; gg += red[2][w]; }
            atomicAdd(&g_l0, a);
            atomicAdd(&g_cacc[bz * NL + layer], c);
            atomicAdd(&g_gacc[bz * NL + layer], gg);
        }
    }
}

// ---------------- attention-pool epilogue ----------------
__global__ void __launch_bounds__(256) k_final(
    const float* __restrict__ F0, const float* __restrict__ projw,
    const float* __restrict__ projb, float* __restrict__ out, float* __restrict__ retain)
{
    const int bn = blockIdx.x;
    const float* p0 = F0 + (size_t)bn * ND;
    const float* p1 = g_F[0] + (size_t)bn * ND;
    const float* p2 = g_F[1] + (size_t)bn * ND;
    const float* p3 = g_F[2] + (size_t)bn * ND;
    const float* p4 = g_F[3] + (size_t)bn * ND;
    float d0 = 0.f, d1 = 0.f, d2 = 0.f, d3 = 0.f, d4 = 0.f;
    for (int i = threadIdx.x; i < ND; i += 256) {
        float w = projw[i];
        d0 += p0[i] * w; d1 += p1[i] * w; d2 += p2[i] * w; d3 += p3[i] * w; d4 += p4[i] * w;
    }
#pragma unroll
    for (int o = 16; o; o >>= 1) {
        d0 += __shfl_xor_sync(0xffffffffu, d0, o);
        d1 += __shfl_xor_sync(0xffffffffu, d1, o);
        d2 += __shfl_xor_sync(0xffffffffu, d2, o);
        d3 += __shfl_xor_sync(0xffffffffu, d3, o);
        d4 += __shfl_xor_sync(0xffffffffu, d4, o);
    }
    __shared__ float sh[5][8], r[5];
    const int wid = threadIdx.x >> 5, lane = threadIdx.x & 31;
    if (lane == 0) { sh[0][wid] = d0; sh[1][wid] = d1; sh[2][wid] = d2; sh[3][wid] = d3; sh[4][wid] = d4; }
    __syncthreads();
    if (threadIdx.x < 5) {
        float t = 0.f;
        for (int w = 0; w < 8; w++) t += sh[threadIdx.x][w];
        float rr = 1.f / (1.f + expf(-(t + projb[0])));
        r[threadIdx.x] = rr;
        retain[(size_t)bn * (NL + 1) + threadIdx.x] = rr;
    }
    __syncthreads();
    const float r0 = r[0], r1 = r[1], r2 = r[2], r3 = r[3], r4 = r[4];
    for (int i = threadIdx.x; i < ND; i += 256)
        out[(size_t)bn * ND + i] = r0 * p0[i] + r1 * p1[i] + r2 * p2[i] + r3 * p3[i] + r4 * p4[i];
}

__global__ void k_repack(float* __restrict__ adjs_out) {
    size_t i = (size_t)blockIdx.x * 256 + threadIdx.x;
    ((float4*)adjs_out)[i] = make_float4(g_adj[0][i], g_adj[1][i], g_adj[2][i], g_adj[3][i]);
}

__global__ void k_finalize(float* __restrict__ o_l0, float* __restrict__ o_c, float* __restrict__ o_g) {
    int t = threadIdx.x;
    if (t == 0) *o_l0 = g_l0 / ((g_fullsum + 1e-8f) * (float)NL);
    if (t < NB * NL) {
        int b = t / NL;
        float ps = g_psum[b];
        o_c[t] = g_cacc[t] / ps;
        o_g[t] = g_gacc[t] / (ps * ps);
    }
}

// ---------------- host orchestration ----------------
extern "C" void kernel_launch(void* const* d_in, const int* in_sizes, int n_in,
                              void* d_out, int out_size)
{
    (void)in_sizes; (void)n_in; (void)out_size;
    const float* pmask   = (const float*)d_in[0];
    const float* feature = (const float*)d_in[1];
    const float* Wq      = (const float*)d_in[2];
    const float* Wk      = (const float*)d_in[3];
    const float* projw   = (const float*)d_in[4];
    const float* projb   = (const float*)d_in[5];

    float* out    = (float*)d_out;
    float* retain = out + FS;
    float* adjs   = retain + (size_t)NB * NN * (NL + 1);
    float* o_l0   = adjs + AS * NL;
    float* o_c    = o_l0 + 1;
    float* o_g    = o_c + NB * NL;

    cudaFuncSetAttribute((const void*)&k_mma<0>, cudaFuncAttributeMaxDynamicSharedMemorySize, SMEM_BYTES);
    cudaFuncSetAttribute((const void*)&k_mma<1>, cudaFuncAttributeMaxDynamicSharedMemorySize, SMEM_BYTES);
    cudaFuncSetAttribute((const void*)&k_mma<2>, cudaFuncAttributeMaxDynamicSharedMemorySize, SMEM_BYTES);

    float *pF, *pAdj;
    __half *pFp, *pWq16, *pWk16, *pMt, *pFt, *paT;
    cudaGetSymbolAddress((void**)&pF, g_F);
    cudaGetSymbolAddress((void**)&pAdj, g_adj);
    cudaGetSymbolAddress((void**)&pFp, g_Fp);
    cudaGetSymbolAddress((void**)&pWq16, g_Wq16);
    cudaGetSymbolAddress((void**)&pWk16, g_Wk16);
    cudaGetSymbolAddress((void**)&pMt, g_Mt);
    cudaGetSymbolAddress((void**)&pFt, g_Ft);
    cudaGetSymbolAddress((void**)&paT, g_aT);

    k_zero<<<256, 256>>>();
    k_init<<<NB, 256>>>(pmask);
    {
        int total = (int)(FS / 4) + 2 * (int)(NL * DD / 4);
        k_cvt3<<<(total + 255) / 256, 256>>>(
            (const float4*)feature, (const float4*)Wq, (const float4*)Wk,
            (__half2*)pFp, (__half2*)pWq16, (__half2*)pWk16);
    }

    // Mt[l] = Wk[l] * Wq[l]^T (fp16), batched over layers
    k_mma<0><<<dim3(ND / BN, ND / BM, NL), 256, SMEM_BYTES>>>(
        pWk16, pWq16, nullptr, pMt, ND, ND, ND, ND, DD, DD, 0, DD, nullptr, 0);

    for (int l = 0; l < NL; l++) {
        // G = F * Mt[l]^T (fp16 into g_Ft scratch)
        k_mma<0><<<dim3(ND / BN, (NB * NN) / BM, 1), 256, SMEM_BYTES>>>(
            pFp, pMt + (size_t)l * DD, nullptr, pFt,
            ND, ND, ND, ND, 0, 0, 0, 0, nullptr, 0);
        // adj = sigmoid(scale * G F^T) * mask (+deg/c/g/l0 + adjT fp16)
        k_mma<1><<<dim3(NN / BN, NN / BM, NB), 256, SMEM_BYTES>>>(
            pFt, pFp, pAdj + (size_t)l * AS, paT,
            ND, ND, ND, NN,
            (size_t)NN * ND, (size_t)NN * ND, (size_t)NN * NN, (size_t)NN * NN, pmask, l);
        // Ft = (F * dis[n])^T fp16 (overwrites G scratch)
        t_ft<<<dim3(ND / 32, NN / 32, NB), dim3(32, 8)>>>(pFp, pFt, l);
        // Fout[m,d] = dis[m] * sum_n adjT[m,n]*Ft[d,n]
        k_mma<2><<<dim3(ND / BN, NN / BM, NB), 256, SMEM_BYTES>>>(
            paT, pFt, pF + (size_t)l * FS, pFp,
            NN, NN, NN, ND,
            (size_t)NN * NN, (size_t)ND * NN, (size_t)NN * ND, (size_t)NN * ND, nullptr, l);
    }

    k_final<<<NB * NN, 256>>>(feature, projw, projb, out, retain);
    k_repack<<<(int)(AS / 256), 256>>>(adjs);
    k_finalize<<<1, 128>>>(o_l0, o_c, o_g);
}